// round 12
// baseline (speedup 1.0000x reference)
#include <cuda_runtime.h>
#include <cuda_bf16.h>
#include <cstdint>
#include <cstddef>

#define BATCH 4
#define SEQ   2048
#define DIM   1024
#define NQKV  3072
#define SCALE 0.03125f   // 1024^-0.5

typedef __nv_bfloat16 bf16;

// ---------------------------------------------------------------------------
// Scratch (static device globals — allocation-free per harness rules)
// ---------------------------------------------------------------------------
__device__ bf16  g_Qh[(size_t)BATCH * SEQ * DIM];   // pre-scaled by SCALE
__device__ bf16  g_Ql[(size_t)BATCH * SEQ * DIM];
__device__ bf16  g_Kh[(size_t)BATCH * SEQ * DIM];
__device__ bf16  g_Kl[(size_t)BATCH * SEQ * DIM];
__device__ bf16  g_Vth[(size_t)BATCH * DIM * SEQ];  // [b, d, t]
__device__ bf16  g_Vtl[(size_t)BATCH * DIM * SEQ];
__device__ float g_S [(size_t)BATCH * SEQ * SEQ];   // scores fp32
__device__ bf16  g_Ph[(size_t)BATCH * SEQ * SEQ];   // softmax probs hi/lo
__device__ bf16  g_Pl[(size_t)BATCH * SEQ * SEQ];

// ---------------------------------------------------------------------------
// helpers
// ---------------------------------------------------------------------------
__device__ __forceinline__ uint32_t smem_u32(const void* p) {
    uint32_t a;
    asm("{ .reg .u64 t; cvta.to.shared.u64 t, %1; cvt.u32.u64 %0, t; }"
        : "=r"(a) : "l"(p));
    return a;
}

__device__ __forceinline__ void ldm4(uint32_t addr, uint32_t& r0, uint32_t& r1,
                                     uint32_t& r2, uint32_t& r3) {
    asm volatile("ldmatrix.sync.aligned.m8n8.x4.shared.b16 {%0,%1,%2,%3}, [%4];"
                 : "=r"(r0), "=r"(r1), "=r"(r2), "=r"(r3) : "r"(addr));
}

__device__ __forceinline__ void mma16816(float* d, const uint32_t* a, const uint32_t* b) {
    asm volatile(
        "mma.sync.aligned.m16n8k16.row.col.f32.bf16.bf16.f32 "
        "{%0,%1,%2,%3}, {%4,%5,%6,%7}, {%8,%9}, {%0,%1,%2,%3};"
        : "+f"(d[0]), "+f"(d[1]), "+f"(d[2]), "+f"(d[3])
        : "r"(a[0]), "r"(a[1]), "r"(a[2]), "r"(a[3]), "r"(b[0]), "r"(b[1]));
}

// smem geometry: rows padded to 40 bf16 (80B) — conflict-free for ldmatrix
#define ROWB        80
#define MAT_BYTES   (128 * ROWB)                 // 10240 B (128 x 32 bf16 tile)
#define STAGE_BYTES (4 * MAT_BYTES)              // Ah | Al | Bh | Bl = 40960 B
#define SMEM_BYTES  (2 * STAGE_BYTES)            // 81920 B; 2 CTAs = 160 KB/SM

// ---------------------------------------------------------------------------
// fp32 half-stage staging (MODE 0): one 128x32 fp32 tile = 8 x 16B / thread.
// fidx = t + i*128, r = fidx>>3, c = fidx&7 — coalesced.
// ---------------------------------------------------------------------------
__device__ __forceinline__ void half_load_f(uint4* v, const float* __restrict__ M,
                                            int K, int rowbase, int kb, int t) {
#pragma unroll
    for (int i = 0; i < 8; i++) {
        const int fidx = t + i * 128;
        const int r = fidx >> 3, c = fidx & 7;
        v[i] = *(const uint4*)(M + (size_t)(rowbase + r) * K + kb + c * 4);
    }
}

__device__ __forceinline__ void cvt_st(const float4 v, uint32_t s_hi, uint32_t s_lo,
                                       uint32_t off) {
    uint32_t h0, h1, l0, l1;
    asm("cvt.rn.satfinite.bf16x2.f32 %0, %1, %2;" : "=r"(h0) : "f"(v.y), "f"(v.x));
    asm("cvt.rn.satfinite.bf16x2.f32 %0, %1, %2;" : "=r"(h1) : "f"(v.w), "f"(v.z));
    const float r0 = v.x - __uint_as_float(h0 << 16);
    const float r1 = v.y - __uint_as_float(h0 & 0xffff0000u);
    const float r2 = v.z - __uint_as_float(h1 << 16);
    const float r3 = v.w - __uint_as_float(h1 & 0xffff0000u);
    asm("cvt.rn.satfinite.bf16x2.f32 %0, %1, %2;" : "=r"(l0) : "f"(r1), "f"(r0));
    asm("cvt.rn.satfinite.bf16x2.f32 %0, %1, %2;" : "=r"(l1) : "f"(r3), "f"(r2));
    asm volatile("st.shared.v2.u32 [%0], {%1, %2};" :: "r"(s_hi + off), "r"(h0), "r"(h1));
    asm volatile("st.shared.v2.u32 [%0], {%1, %2};" :: "r"(s_lo + off), "r"(l0), "r"(l1));
}

__device__ __forceinline__ void half_store_f(const uint4* v, uint32_t s_hi,
                                             uint32_t s_lo, int t) {
#pragma unroll
    for (int i = 0; i < 8; i++) {
        const int fidx = t + i * 128;
        const int r = fidx >> 3, c = fidx & 7;
        const float4 f = *(const float4*)&v[i];
        cvt_st(f, s_hi, s_lo, (uint32_t)(r * ROWB + c * 8));
    }
}

// ---------------------------------------------------------------------------
// Pre-split bf16 staging (MODES 1,2): hi and lo tiles are 128x32 bf16 = 8 KB
// each; 4 x 16B chunks per thread per tile. fidx = t + i*128, r = fidx>>2,
// c = fidx&3 — warp covers 8 full 64B rows (perfect coalescing).
// ---------------------------------------------------------------------------
__device__ __forceinline__ void half_load_b(uint4* v,
                                            const bf16* __restrict__ hi,
                                            const bf16* __restrict__ lo,
                                            int K, int rowbase, int kb, int t) {
#pragma unroll
    for (int i = 0; i < 4; i++) {
        const int fidx = t + i * 128;
        const int r = fidx >> 2, c = fidx & 3;
        const size_t o = (size_t)(rowbase + r) * K + kb + c * 8;
        v[i]     = *(const uint4*)(hi + o);
        v[4 + i] = *(const uint4*)(lo + o);
    }
}

__device__ __forceinline__ void half_store_b(const uint4* v, uint32_t s_hi,
                                             uint32_t s_lo, int t) {
#pragma unroll
    for (int i = 0; i < 4; i++) {
        const int fidx = t + i * 128;
        const int r = fidx >> 2, c = fidx & 3;
        const uint32_t off = (uint32_t)(r * ROWB + c * 16);
        const uint4 a = v[i], b = v[4 + i];
        asm volatile("st.shared.v4.b32 [%0], {%1, %2, %3, %4};"
                     :: "r"(s_hi + off), "r"(a.x), "r"(a.y), "r"(a.z), "r"(a.w));
        asm volatile("st.shared.v4.b32 [%0], {%1, %2, %3, %4};"
                     :: "r"(s_lo + off), "r"(b.x), "r"(b.y), "r"(b.z), "r"(b.w));
    }
}

// ---------------------------------------------------------------------------
// bf16-split tensor-core GEMM: C[128,128] = A[M,K] * B[N,K]^T  (both K-major)
// 4 warps (warp tile 64x64), 128 threads, 2 CTAs/SM. R9-proven mainloop.
// MODE 0: X @ W^T (fp32 in-loop split) -> emit Qh/Ql(*SCALE), Kh/Kl, Vth/Vtl
// MODE 1: Q @ K^T (pre-split operands) -> g_S   (scale folded into Q)
// MODE 2: P @ Vt^T (pre-split operands) -> out
// ---------------------------------------------------------------------------
template <int MODE>
__global__ __launch_bounds__(128) void mma_gemm(const float* __restrict__ X,
                                                const float* __restrict__ W,
                                                float* __restrict__ Out) {
    extern __shared__ char smem[];
    const uint32_t sm = smem_u32(smem);
    const int t = threadIdx.x;
    const int wid = t >> 5;
    const int l = t & 31;
    const int z = blockIdx.z;

    const float* A32 = nullptr;
    const float* B32 = nullptr;
    const bf16 *Ahi = nullptr, *Alo = nullptr, *Bhi = nullptr, *Blo = nullptr;
    float* C = nullptr;
    int K;
    if (MODE == 0) {
        A32 = X; B32 = W; K = DIM;
    } else if (MODE == 1) {
        Ahi = g_Qh + (size_t)z * SEQ * DIM;  Alo = g_Ql + (size_t)z * SEQ * DIM;
        Bhi = g_Kh + (size_t)z * SEQ * DIM;  Blo = g_Kl + (size_t)z * SEQ * DIM;
        C = g_S + (size_t)z * SEQ * SEQ;     K = DIM;
    } else {
        Ahi = g_Ph + (size_t)z * SEQ * SEQ;  Alo = g_Pl + (size_t)z * SEQ * SEQ;
        Bhi = g_Vth + (size_t)z * DIM * SEQ; Blo = g_Vtl + (size_t)z * DIM * SEQ;
        C = Out + (size_t)z * SEQ * DIM;     K = SEQ;
    }

    const int row0 = blockIdx.y * 128;
    const int col0 = blockIdx.x * 128;
    const int KI = K / 32;

    const int wm = (wid >> 1) * 64;     // warp M offset (2x2 warp grid)
    const int wn = (wid & 1) * 64;      // warp N offset (64-wide)

    const int a_row = l & 15;
    const int a_koff = ((l >> 4) & 1) * 8;
    const int b_row = (l & 7) + ((l >> 4) & 1) * 8;
    const int b_koff = ((l >> 3) & 1) * 8;

    float acc[4][8][4];                 // 128 regs
#pragma unroll
    for (int mi = 0; mi < 4; mi++)
#pragma unroll
        for (int ni = 0; ni < 8; ni++)
#pragma unroll
            for (int j = 0; j < 4; j++) acc[mi][ni][j] = 0.0f;

    uint4 pf[8];                        // half-stage prefetch buffer (32 regs)

    // prologue: stage 0 (A then B halves)
    if (MODE == 0) {
        half_load_f(pf, A32, K, row0, 0, t);
        half_store_f(pf, sm, sm + MAT_BYTES, t);
        half_load_f(pf, B32, K, col0, 0, t);
        half_store_f(pf, sm + 2 * MAT_BYTES, sm + 3 * MAT_BYTES, t);
    } else {
        half_load_b(pf, Ahi, Alo, K, row0, 0, t);
        half_store_b(pf, sm, sm + MAT_BYTES, t);
        half_load_b(pf, Bhi, Blo, K, col0, 0, t);
        half_store_b(pf, sm + 2 * MAT_BYTES, sm + 3 * MAT_BYTES, t);
    }
    __syncthreads();

    for (int it = 0; it < KI; it++) {
        const int s = it & 1;
        const uint32_t stg = sm + s * STAGE_BYTES;
        const uint32_t nstg = sm + (1 - s) * STAGE_BYTES;
        const bool pfv = (it + 1 < KI);
        const int kb = (it + 1) * 32;

        // prefetch A-half for next iter (latency covered by k0=0 compute)
        if (pfv) {
            if (MODE == 0) half_load_f(pf, A32, K, row0, kb, t);
            else           half_load_b(pf, Ahi, Alo, K, row0, kb, t);
        }

        const uint32_t sAh = stg;
        const uint32_t sAl = stg + MAT_BYTES;
        const uint32_t sBh = stg + 2 * MAT_BYTES;
        const uint32_t sBl = stg + 3 * MAT_BYTES;

#pragma unroll
        for (int k0 = 0; k0 < 32; k0 += 16) {
            uint32_t bH[8][2], bL[8][2];
#pragma unroll
            for (int nb = 0; nb < 4; nb++) {
                const uint32_t off =
                    (uint32_t)((wn + nb * 16 + b_row) * ROWB + (k0 + b_koff) * 2);
                uint32_t r0, r1, r2, r3;
                ldm4(sBh + off, r0, r1, r2, r3);
                bH[2 * nb][0] = r0; bH[2 * nb][1] = r1;
                bH[2 * nb + 1][0] = r2; bH[2 * nb + 1][1] = r3;
                ldm4(sBl + off, r0, r1, r2, r3);
                bL[2 * nb][0] = r0; bL[2 * nb][1] = r1;
                bL[2 * nb + 1][0] = r2; bL[2 * nb + 1][1] = r3;
            }
#pragma unroll
            for (int mi = 0; mi < 4; mi++) {
                uint32_t aH[4], aL[4];
                const uint32_t off =
                    (uint32_t)((wm + mi * 16 + a_row) * ROWB + (k0 + a_koff) * 2);
                ldm4(sAh + off, aH[0], aH[1], aH[2], aH[3]);
                ldm4(sAl + off, aL[0], aL[1], aL[2], aL[3]);
#pragma unroll
                for (int ni = 0; ni < 8; ni++) {
                    mma16816(acc[mi][ni], aH, bH[ni]);
                    mma16816(acc[mi][ni], aH, bL[ni]);
                    mma16816(acc[mi][ni], aL, bH[ni]);
                }
            }

            // between the two k0 steps: store A-half, start B-half prefetch
            if (k0 == 0 && pfv) {
                if (MODE == 0) {
                    half_store_f(pf, nstg, nstg + MAT_BYTES, t);
                    half_load_f(pf, B32, K, col0, kb, t);
                } else {
                    half_store_b(pf, nstg, nstg + MAT_BYTES, t);
                    half_load_b(pf, Bhi, Blo, K, col0, kb, t);
                }
            }
        }

        if (pfv) {
            if (MODE == 0) half_store_f(pf, nstg + 2 * MAT_BYTES, nstg + 3 * MAT_BYTES, t);
            else           half_store_b(pf, nstg + 2 * MAT_BYTES, nstg + 3 * MAT_BYTES, t);
        }
        __syncthreads();
    }

    // Epilogue: fragments -> padded smem -> (scatter) gmem
    float* Csh = (float*)smem;                     // 128 x 130 fp32 (66.6 KB)
#pragma unroll
    for (int mi = 0; mi < 4; mi++)
#pragma unroll
        for (int ni = 0; ni < 8; ni++) {
            const int r = wm + mi * 16 + (l >> 2);
            const int c = wn + ni * 8 + (l & 3) * 2;
            Csh[r * 130 + c]           = acc[mi][ni][0];
            Csh[r * 130 + c + 1]       = acc[mi][ni][1];
            Csh[(r + 8) * 130 + c]     = acc[mi][ni][2];
            Csh[(r + 8) * 130 + c + 1] = acc[mi][ni][3];
        }
    __syncthreads();

    for (int i = t; i < 128 * 128; i += 128) {
        const int r = i >> 7, c = i & 127;
        const float v = Csh[r * 130 + c];
        if (MODE == 0) {
            const int grow = row0 + r;
            const int col = col0 + c;
            const int which = col % 3;             // qkv reshape (d,3)
            const int oc = col / 3;
            if (which == 0) {
                const size_t o = (size_t)grow * DIM + oc;
                const float q = v * SCALE;         // fold attention scale into Q
                const bf16 h = __float2bfloat16(q);
                g_Qh[o] = h;
                g_Ql[o] = __float2bfloat16(q - __bfloat162float(h));
            } else if (which == 1) {
                const size_t o = (size_t)grow * DIM + oc;
                const bf16 h = __float2bfloat16(v);
                g_Kh[o] = h;
                g_Kl[o] = __float2bfloat16(v - __bfloat162float(h));
            } else {
                const int b = grow >> 11, tt = grow & 2047;
                const size_t o = ((size_t)b * DIM + oc) * SEQ + tt;
                const bf16 h = __float2bfloat16(v);
                g_Vth[o] = h;
                g_Vtl[o] = __float2bfloat16(v - __bfloat162float(h));
            }
        } else if (MODE == 1) {
            C[(size_t)(row0 + r) * SEQ + col0 + c] = v;   // raw scores (scale in Q)
        } else {
            C[(size_t)(row0 + r) * DIM + col0 + c] = v;
        }
    }
}

// ---------------------------------------------------------------------------
// Row softmax: g_S row (2048 fp32) -> P hi/lo bf16. 8 consecutive per thread.
// ---------------------------------------------------------------------------
__global__ __launch_bounds__(256) void softmax_k() {
    const size_t base = (size_t)blockIdx.x * SEQ;
    const float* p = g_S + base;
    const int t = threadIdx.x;
    const int lane = t & 31;
    const int warp = t >> 5;
    __shared__ float red[2][8];

    const float4 a = *(const float4*)(p + t * 8);
    const float4 b = *(const float4*)(p + t * 8 + 4);
    float v[8] = {a.x, a.y, a.z, a.w, b.x, b.y, b.z, b.w};

    float m = -1e30f;
#pragma unroll
    for (int i = 0; i < 8; i++) m = fmaxf(m, v[i]);
#pragma unroll
    for (int off = 16; off > 0; off >>= 1)
        m = fmaxf(m, __shfl_xor_sync(0xffffffffu, m, off));
    if (lane == 0) red[0][warp] = m;
    __syncthreads();
    m = red[0][0];
#pragma unroll
    for (int w = 1; w < 8; w++) m = fmaxf(m, red[0][w]);

    float s = 0.0f;
#pragma unroll
    for (int i = 0; i < 8; i++) { v[i] = __expf(v[i] - m); s += v[i]; }
#pragma unroll
    for (int off = 16; off > 0; off >>= 1)
        s += __shfl_xor_sync(0xffffffffu, s, off);
    if (lane == 0) red[1][warp] = s;
    __syncthreads();
    s = red[1][0];
#pragma unroll
    for (int w = 1; w < 8; w++) s += red[1][w];

    const float inv = 1.0f / s;
    bf16 h[8], lo[8];
#pragma unroll
    for (int i = 0; i < 8; i++) {
        const float q = v[i] * inv;
        h[i] = __float2bfloat16(q);
        lo[i] = __float2bfloat16(q - __bfloat162float(h[i]));
    }
    *(uint4*)(g_Ph + base + t * 8) = *(const uint4*)h;
    *(uint4*)(g_Pl + base + t * 8) = *(const uint4*)lo;
}

// ---------------------------------------------------------------------------
extern "C" void kernel_launch(void* const* d_in, const int* in_sizes, int n_in,
                              void* d_out, int out_size) {
    const float* x = (const float*)d_in[0];    // [4, 2048, 1024]
    const float* W = (const float*)d_in[1];    // [3072, 1024]
    float* out = (float*)d_out;                // [4, 2048, 1024]

    cudaFuncSetAttribute(mma_gemm<0>, cudaFuncAttributeMaxDynamicSharedMemorySize, SMEM_BYTES);
    cudaFuncSetAttribute(mma_gemm<1>, cudaFuncAttributeMaxDynamicSharedMemorySize, SMEM_BYTES);
    cudaFuncSetAttribute(mma_gemm<2>, cudaFuncAttributeMaxDynamicSharedMemorySize, SMEM_BYTES);

    // 1) QKV projection (epilogue emits Q/K hi-lo pairs and transposed V pair)
    mma_gemm<0><<<dim3(NQKV / 128, (BATCH * SEQ) / 128, 1), 128, SMEM_BYTES>>>(x, W, nullptr);
    // 2) scores = (Q*scale) K^T  (pre-split operands, pure-copy staging)
    mma_gemm<1><<<dim3(SEQ / 128, SEQ / 128, BATCH), 128, SMEM_BYTES>>>(nullptr, nullptr, nullptr);
    // 3) softmax -> P hi/lo
    softmax_k<<<dim3(BATCH * SEQ), 256>>>();
    // 4) out = P V  (pre-split operands, pure-copy staging)
    mma_gemm<2><<<dim3(DIM / 128, SEQ / 128, BATCH), 128, SMEM_BYTES>>>(nullptr, nullptr, out);
}

// round 13
// speedup vs baseline: 1.0208x; 1.0208x over previous
#include <cuda_runtime.h>
#include <cuda_bf16.h>
#include <cstdint>
#include <cstddef>

#define BATCH 4
#define SEQ   2048
#define DIM   1024
#define NQKV  3072
#define SCALE 0.03125f   // 1024^-0.5

#define NPERSIST 296     // 2 CTAs/SM x 148 SMs — one full resident wave

// Scratch (static device globals — allocation-free per harness rules)
__device__ float g_Q [(size_t)BATCH * SEQ * DIM];   // [b*t, d]
__device__ float g_K [(size_t)BATCH * SEQ * DIM];   // [b*t, d]
__device__ float g_Vt[(size_t)BATCH * DIM * SEQ];   // [b, d, t] (transposed V)
__device__ float g_S [(size_t)BATCH * SEQ * SEQ];   // [b, t, t]

// ---------------------------------------------------------------------------
// helpers
// ---------------------------------------------------------------------------
__device__ __forceinline__ uint32_t smem_u32(const void* p) {
    uint32_t a;
    asm("{ .reg .u64 t; cvta.to.shared.u64 t, %1; cvt.u32.u64 %0, t; }"
        : "=r"(a) : "l"(p));
    return a;
}

__device__ __forceinline__ void ldm4(uint32_t addr, uint32_t& r0, uint32_t& r1,
                                     uint32_t& r2, uint32_t& r3) {
    asm volatile("ldmatrix.sync.aligned.m8n8.x4.shared.b16 {%0,%1,%2,%3}, [%4];"
                 : "=r"(r0), "=r"(r1), "=r"(r2), "=r"(r3) : "r"(addr));
}

__device__ __forceinline__ void mma16816(float* d, const uint32_t* a, const uint32_t* b) {
    asm volatile(
        "mma.sync.aligned.m16n8k16.row.col.f32.bf16.bf16.f32 "
        "{%0,%1,%2,%3}, {%4,%5,%6,%7}, {%8,%9}, {%0,%1,%2,%3};"
        : "+f"(d[0]), "+f"(d[1]), "+f"(d[2]), "+f"(d[3])
        : "r"(a[0]), "r"(a[1]), "r"(a[2]), "r"(a[3]), "r"(b[0]), "r"(b[1]));
}

// smem geometry: rows padded to 40 bf16 (80B) — conflict-free for ldmatrix
#define ROWB        80
#define MAT_BYTES   (128 * ROWB)                 // 10240 B (128 x 32 bf16 tile)
#define STAGE_BYTES (4 * MAT_BYTES)              // Ah | Al | Bh | Bl = 40960 B
#define SMEM_BYTES  (2 * STAGE_BYTES)            // 81920 B; 2 CTAs = 160 KB/SM

// ---------------------------------------------------------------------------
// Half-stage register staging (128 threads): one 128x32 fp32 tile = 8 x 16B
// chunks per thread. fidx = t + i*128, r = fidx>>3, c = fidx&7 (coalesced).
// ---------------------------------------------------------------------------
__device__ __forceinline__ void half_load(float4* v, const float* __restrict__ M,
                                          int K, int row0, int kb, int t) {
#pragma unroll
    for (int i = 0; i < 8; i++) {
        const int fidx = t + i * 128;
        const int r = fidx >> 3, c = fidx & 7;
        v[i] = *(const float4*)(M + (size_t)(row0 + r) * K + kb + c * 4);
    }
}

__device__ __forceinline__ void cvt_st(const float4 v, uint32_t s_hi, uint32_t s_lo,
                                       uint32_t off) {
    uint32_t h0, h1, l0, l1;
    asm("cvt.rn.satfinite.bf16x2.f32 %0, %1, %2;" : "=r"(h0) : "f"(v.y), "f"(v.x));
    asm("cvt.rn.satfinite.bf16x2.f32 %0, %1, %2;" : "=r"(h1) : "f"(v.w), "f"(v.z));
    const float r0 = v.x - __uint_as_float(h0 << 16);
    const float r1 = v.y - __uint_as_float(h0 & 0xffff0000u);
    const float r2 = v.z - __uint_as_float(h1 << 16);
    const float r3 = v.w - __uint_as_float(h1 & 0xffff0000u);
    asm("cvt.rn.satfinite.bf16x2.f32 %0, %1, %2;" : "=r"(l0) : "f"(r1), "f"(r0));
    asm("cvt.rn.satfinite.bf16x2.f32 %0, %1, %2;" : "=r"(l1) : "f"(r3), "f"(r2));
    asm volatile("st.shared.v2.u32 [%0], {%1, %2};" :: "r"(s_hi + off), "r"(h0), "r"(h1));
    asm volatile("st.shared.v2.u32 [%0], {%1, %2};" :: "r"(s_lo + off), "r"(l0), "r"(l1));
}

__device__ __forceinline__ void half_store(const float4* v, uint32_t s_hi,
                                           uint32_t s_lo, int t) {
#pragma unroll
    for (int i = 0; i < 8; i++) {
        const int fidx = t + i * 128;
        const int r = fidx >> 3, c = fidx & 7;
        cvt_st(v[i], s_hi, s_lo, (uint32_t)(r * ROWB + c * 8));
    }
}

// ---------------------------------------------------------------------------
// Persistent bf16-split tensor-core GEMM: C[128,128] tiles of A[M,K]*B[N,K]^T.
// 4 warps (warp tile 64x64), 128 threads, 2 CTAs/SM; exactly NPERSIST CTAs
// grid-stride over the flattened (z, ty, tx) tile list — no partial waves.
// MODE 0: X @ W^T  -> scatter to g_Q / g_K / g_Vt(transposed)   [tiles 1536]
// MODE 1: Q @ K^T * scale -> g_S   (per batch)                  [tiles 1024]
// MODE 2: P @ Vt^T -> out          (per batch)                  [tiles  512]
// ---------------------------------------------------------------------------
template <int MODE>
__global__ __launch_bounds__(128) void mma_gemm(const float* __restrict__ X,
                                                const float* __restrict__ W,
                                                float* __restrict__ Out) {
    extern __shared__ char smem[];
    const uint32_t sm = smem_u32(smem);
    const int t = threadIdx.x;
    const int wid = t >> 5;
    const int l = t & 31;

    const int GX = (MODE == 0) ? (NQKV / 128) : (MODE == 1) ? (SEQ / 128) : (DIM / 128);
    const int GY = (MODE == 0) ? ((BATCH * SEQ) / 128) : (SEQ / 128);
    const int GZ = (MODE == 0) ? 1 : BATCH;
    const int NTILES = GX * GY * GZ;

    const int wm = (wid >> 1) * 64;     // warp M offset (2x2 warp grid)
    const int wn = (wid & 1) * 64;      // warp N offset (64-wide)

    const int a_row = l & 15;
    const int a_koff = ((l >> 4) & 1) * 8;
    const int b_row = (l & 7) + ((l >> 4) & 1) * 8;
    const int b_koff = ((l >> 3) & 1) * 8;

    for (int tile = blockIdx.x; tile < NTILES; tile += NPERSIST) {
        const int tx = tile % GX;
        const int ty = (tile / GX) % GY;
        const int z  = tile / (GX * GY);

        const float* A;
        const float* B;
        float* C = nullptr;
        int K;
        if (MODE == 0) { A = X; B = W; K = DIM; }
        else if (MODE == 1) {
            A = g_Q + (size_t)z * SEQ * DIM;
            B = g_K + (size_t)z * SEQ * DIM;
            C = g_S + (size_t)z * SEQ * SEQ;
            K = DIM;
        } else {
            A = g_S  + (size_t)z * SEQ * SEQ;
            B = g_Vt + (size_t)z * DIM * SEQ;
            C = Out  + (size_t)z * SEQ * DIM;
            K = SEQ;
        }

        const int row0 = ty * 128;
        const int col0 = tx * 128;
        const int KI = K / 32;

        float acc[4][8][4];             // 128 regs
#pragma unroll
        for (int mi = 0; mi < 4; mi++)
#pragma unroll
            for (int ni = 0; ni < 8; ni++)
#pragma unroll
                for (int j = 0; j < 4; j++) acc[mi][ni][j] = 0.0f;

        float4 pf[8];                   // half-stage prefetch buffer

        // prologue: stage 0 (A then B halves)
        half_load(pf, A, K, row0, 0, t);
        half_store(pf, sm, sm + MAT_BYTES, t);
        half_load(pf, B, K, col0, 0, t);
        half_store(pf, sm + 2 * MAT_BYTES, sm + 3 * MAT_BYTES, t);
        __syncthreads();

        for (int it = 0; it < KI; it++) {
            const int s = it & 1;
            const uint32_t stg = sm + s * STAGE_BYTES;
            const uint32_t nstg = sm + (1 - s) * STAGE_BYTES;
            const bool pfv = (it + 1 < KI);
            const int kb = (it + 1) * 32;

            // prefetch A-half for next iter (covered by k0=0 compute)
            if (pfv) half_load(pf, A, K, row0, kb, t);

            const uint32_t sAh = stg;
            const uint32_t sAl = stg + MAT_BYTES;
            const uint32_t sBh = stg + 2 * MAT_BYTES;
            const uint32_t sBl = stg + 3 * MAT_BYTES;

#pragma unroll
            for (int k0 = 0; k0 < 32; k0 += 16) {
                uint32_t bH[8][2], bL[8][2];
#pragma unroll
                for (int nb = 0; nb < 4; nb++) {
                    const uint32_t off =
                        (uint32_t)((wn + nb * 16 + b_row) * ROWB + (k0 + b_koff) * 2);
                    uint32_t r0, r1, r2, r3;
                    ldm4(sBh + off, r0, r1, r2, r3);
                    bH[2 * nb][0] = r0; bH[2 * nb][1] = r1;
                    bH[2 * nb + 1][0] = r2; bH[2 * nb + 1][1] = r3;
                    ldm4(sBl + off, r0, r1, r2, r3);
                    bL[2 * nb][0] = r0; bL[2 * nb][1] = r1;
                    bL[2 * nb + 1][0] = r2; bL[2 * nb + 1][1] = r3;
                }
#pragma unroll
                for (int mi = 0; mi < 4; mi++) {
                    uint32_t aH[4], aL[4];
                    const uint32_t off =
                        (uint32_t)((wm + mi * 16 + a_row) * ROWB + (k0 + a_koff) * 2);
                    ldm4(sAh + off, aH[0], aH[1], aH[2], aH[3]);
                    ldm4(sAl + off, aL[0], aL[1], aL[2], aL[3]);
#pragma unroll
                    for (int ni = 0; ni < 8; ni++) {
                        mma16816(acc[mi][ni], aH, bH[ni]);
                        mma16816(acc[mi][ni], aH, bL[ni]);
                        mma16816(acc[mi][ni], aL, bH[ni]);
                    }
                }

                // between the two k0 steps: store A-half, start B-half prefetch
                if (k0 == 0 && pfv) {
                    half_store(pf, nstg, nstg + MAT_BYTES, t);
                    half_load(pf, B, K, col0, kb, t);
                }
            }

            if (pfv) half_store(pf, nstg + 2 * MAT_BYTES, nstg + 3 * MAT_BYTES, t);
            __syncthreads();
        }

        // Epilogue: fragments -> padded smem -> (scatter) gmem
        float* Csh = (float*)smem;                 // 128 x 130 fp32 (66.6 KB)
#pragma unroll
        for (int mi = 0; mi < 4; mi++)
#pragma unroll
            for (int ni = 0; ni < 8; ni++) {
                const int r = wm + mi * 16 + (l >> 2);
                const int c = wn + ni * 8 + (l & 3) * 2;
                float d0 = acc[mi][ni][0], d1 = acc[mi][ni][1];
                float d2 = acc[mi][ni][2], d3 = acc[mi][ni][3];
                if (MODE == 1) { d0 *= SCALE; d1 *= SCALE; d2 *= SCALE; d3 *= SCALE; }
                Csh[r * 130 + c]           = d0;
                Csh[r * 130 + c + 1]       = d1;
                Csh[(r + 8) * 130 + c]     = d2;
                Csh[(r + 8) * 130 + c + 1] = d3;
            }
        __syncthreads();

        for (int i = t; i < 128 * 128; i += 128) {
            const int r = i >> 7, c = i & 127;
            const float v = Csh[r * 130 + c];
            if (MODE == 0) {
                const int grow = row0 + r;
                const int col = col0 + c;
                const int which = col % 3;         // qkv reshape (d,3)
                const int oc = col / 3;
                if (which == 0)      g_Q[(size_t)grow * DIM + oc] = v;
                else if (which == 1) g_K[(size_t)grow * DIM + oc] = v;
                else {
                    const int b = grow >> 11, tt = grow & 2047;
                    g_Vt[((size_t)b * DIM + oc) * SEQ + tt] = v;
                }
            } else if (MODE == 1) {
                C[(size_t)(row0 + r) * SEQ + col0 + c] = v;
            } else {
                C[(size_t)(row0 + r) * DIM + col0 + c] = v;
            }
        }
        __syncthreads();   // smem reused by next tile's prologue
    }
}

// ---------------------------------------------------------------------------
// Row softmax over g_S: one block (256 threads) per row of length 2048.
// ---------------------------------------------------------------------------
__global__ __launch_bounds__(256) void softmax_k() {
    float* p = g_S + (size_t)blockIdx.x * SEQ;
    const int t = threadIdx.x;
    const int lane = t & 31;
    const int warp = t >> 5;
    __shared__ float red[2][8];

    float v[8];
    float m = -1e30f;
#pragma unroll
    for (int i = 0; i < 8; i++) { v[i] = p[t + i * 256]; m = fmaxf(m, v[i]); }
#pragma unroll
    for (int off = 16; off > 0; off >>= 1)
        m = fmaxf(m, __shfl_xor_sync(0xffffffffu, m, off));
    if (lane == 0) red[0][warp] = m;
    __syncthreads();
    m = red[0][0];
#pragma unroll
    for (int w = 1; w < 8; w++) m = fmaxf(m, red[0][w]);

    float s = 0.0f;
#pragma unroll
    for (int i = 0; i < 8; i++) { v[i] = __expf(v[i] - m); s += v[i]; }
#pragma unroll
    for (int off = 16; off > 0; off >>= 1)
        s += __shfl_xor_sync(0xffffffffu, s, off);
    if (lane == 0) red[1][warp] = s;
    __syncthreads();
    s = red[1][0];
#pragma unroll
    for (int w = 1; w < 8; w++) s += red[1][w];

    const float inv = 1.0f / s;
#pragma unroll
    for (int i = 0; i < 8; i++) p[t + i * 256] = v[i] * inv;
}

// ---------------------------------------------------------------------------
extern "C" void kernel_launch(void* const* d_in, const int* in_sizes, int n_in,
                              void* d_out, int out_size) {
    const float* x = (const float*)d_in[0];    // [4, 2048, 1024]
    const float* W = (const float*)d_in[1];    // [3072, 1024]
    float* out = (float*)d_out;                // [4, 2048, 1024]

    cudaFuncSetAttribute(mma_gemm<0>, cudaFuncAttributeMaxDynamicSharedMemorySize, SMEM_BYTES);
    cudaFuncSetAttribute(mma_gemm<1>, cudaFuncAttributeMaxDynamicSharedMemorySize, SMEM_BYTES);
    cudaFuncSetAttribute(mma_gemm<2>, cudaFuncAttributeMaxDynamicSharedMemorySize, SMEM_BYTES);

    // 1) QKV projection (scatter epilogue de-interleaves into Q / K / V^T)
    mma_gemm<0><<<NPERSIST, 128, SMEM_BYTES>>>(x, W, nullptr);
    // 2) scores = Q K^T * scale
    mma_gemm<1><<<NPERSIST, 128, SMEM_BYTES>>>(nullptr, nullptr, nullptr);
    // 3) row softmax
    softmax_k<<<dim3(BATCH * SEQ), 256>>>();
    // 4) out = P V
    mma_gemm<2><<<NPERSIST, 128, SMEM_BYTES>>>(nullptr, nullptr, out);
}

// round 14
// speedup vs baseline: 1.0318x; 1.0107x over previous
#include <cuda_runtime.h>
#include <cuda_bf16.h>
#include <cstdint>
#include <cstddef>

#define BATCH 4
#define SEQ   2048
#define DIM   1024
#define NQKV  3072
#define SCALE 0.03125f   // 1024^-0.5

typedef __nv_bfloat16 bf16;

// Scratch (static device globals — allocation-free per harness rules)
__device__ float g_Q [(size_t)BATCH * SEQ * DIM];   // [b*t, d]
__device__ float g_K [(size_t)BATCH * SEQ * DIM];   // [b*t, d]
__device__ float g_Vt[(size_t)BATCH * DIM * SEQ];   // [b, d, t] (transposed V)
__device__ float g_S [(size_t)BATCH * SEQ * SEQ];   // [b, t, t] raw scores
__device__ bf16  g_Ph[(size_t)BATCH * SEQ * SEQ];   // softmax probs hi
__device__ bf16  g_Pl[(size_t)BATCH * SEQ * SEQ];   // softmax probs lo

// ---------------------------------------------------------------------------
// helpers
// ---------------------------------------------------------------------------
__device__ __forceinline__ uint32_t smem_u32(const void* p) {
    uint32_t a;
    asm("{ .reg .u64 t; cvta.to.shared.u64 t, %1; cvt.u32.u64 %0, t; }"
        : "=r"(a) : "l"(p));
    return a;
}

__device__ __forceinline__ void ldm4(uint32_t addr, uint32_t& r0, uint32_t& r1,
                                     uint32_t& r2, uint32_t& r3) {
    asm volatile("ldmatrix.sync.aligned.m8n8.x4.shared.b16 {%0,%1,%2,%3}, [%4];"
                 : "=r"(r0), "=r"(r1), "=r"(r2), "=r"(r3) : "r"(addr));
}

__device__ __forceinline__ void mma16816(float* d, const uint32_t* a, const uint32_t* b) {
    asm volatile(
        "mma.sync.aligned.m16n8k16.row.col.f32.bf16.bf16.f32 "
        "{%0,%1,%2,%3}, {%4,%5,%6,%7}, {%8,%9}, {%0,%1,%2,%3};"
        : "+f"(d[0]), "+f"(d[1]), "+f"(d[2]), "+f"(d[3])
        : "r"(a[0]), "r"(a[1]), "r"(a[2]), "r"(a[3]), "r"(b[0]), "r"(b[1]));
}

// smem geometry: rows padded to 40 bf16 (80B) — conflict-free for ldmatrix
#define ROWB        80
#define MAT_BYTES   (128 * ROWB)                 // 10240 B (128 x 32 bf16 tile)
#define STAGE_BYTES (4 * MAT_BYTES)              // Ah | Al | Bh | Bl = 40960 B
#define SMEM_BYTES  (2 * STAGE_BYTES)            // 81920 B; 2 CTAs = 160 KB/SM

// ---------------------------------------------------------------------------
// fp32 half-stage staging: one 128x32 fp32 tile = 8 x 16B chunks per thread.
// fidx = t + i*128, r = fidx>>3, c = fidx&7 (coalesced, 8 thr per 128B row).
// ---------------------------------------------------------------------------
__device__ __forceinline__ void half_load(float4* v, const float* __restrict__ M,
                                          int K, int row0, int kb, int t) {
#pragma unroll
    for (int i = 0; i < 8; i++) {
        const int fidx = t + i * 128;
        const int r = fidx >> 3, c = fidx & 7;
        v[i] = *(const float4*)(M + (size_t)(row0 + r) * K + kb + c * 4);
    }
}

__device__ __forceinline__ void cvt_st(const float4 v, uint32_t s_hi, uint32_t s_lo,
                                       uint32_t off) {
    uint32_t h0, h1, l0, l1;
    asm("cvt.rn.satfinite.bf16x2.f32 %0, %1, %2;" : "=r"(h0) : "f"(v.y), "f"(v.x));
    asm("cvt.rn.satfinite.bf16x2.f32 %0, %1, %2;" : "=r"(h1) : "f"(v.w), "f"(v.z));
    const float r0 = v.x - __uint_as_float(h0 << 16);
    const float r1 = v.y - __uint_as_float(h0 & 0xffff0000u);
    const float r2 = v.z - __uint_as_float(h1 << 16);
    const float r3 = v.w - __uint_as_float(h1 & 0xffff0000u);
    asm("cvt.rn.satfinite.bf16x2.f32 %0, %1, %2;" : "=r"(l0) : "f"(r1), "f"(r0));
    asm("cvt.rn.satfinite.bf16x2.f32 %0, %1, %2;" : "=r"(l1) : "f"(r3), "f"(r2));
    asm volatile("st.shared.v2.u32 [%0], {%1, %2};" :: "r"(s_hi + off), "r"(h0), "r"(h1));
    asm volatile("st.shared.v2.u32 [%0], {%1, %2};" :: "r"(s_lo + off), "r"(l0), "r"(l1));
}

__device__ __forceinline__ void half_store(const float4* v, uint32_t s_hi,
                                           uint32_t s_lo, int t) {
#pragma unroll
    for (int i = 0; i < 8; i++) {
        const int fidx = t + i * 128;
        const int r = fidx >> 3, c = fidx & 7;
        cvt_st(v[i], s_hi, s_lo, (uint32_t)(r * ROWB + c * 8));
    }
}

// ---------------------------------------------------------------------------
// Pre-split bf16 half-stage staging (mode2 A operand): hi and lo tiles are
// 128x32 bf16 = 8 KB each; 4 x 16B chunks per thread per tile.
// fidx = t + i*128, r = fidx>>2, c = fidx&3 — warp covers 8 full 64B rows.
// ---------------------------------------------------------------------------
__device__ __forceinline__ void half_load_b(uint4* v,
                                            const bf16* __restrict__ hi,
                                            const bf16* __restrict__ lo,
                                            int K, int row0, int kb, int t) {
#pragma unroll
    for (int i = 0; i < 4; i++) {
        const int fidx = t + i * 128;
        const int r = fidx >> 2, c = fidx & 3;
        const size_t o = (size_t)(row0 + r) * K + kb + c * 8;
        v[i]     = *(const uint4*)(hi + o);
        v[4 + i] = *(const uint4*)(lo + o);
    }
}

__device__ __forceinline__ void half_store_b(const uint4* v, uint32_t s_hi,
                                             uint32_t s_lo, int t) {
#pragma unroll
    for (int i = 0; i < 4; i++) {
        const int fidx = t + i * 128;
        const int r = fidx >> 2, c = fidx & 3;
        const uint32_t off = (uint32_t)(r * ROWB + c * 16);
        const uint4 a = v[i], b = v[4 + i];
        asm volatile("st.shared.v4.b32 [%0], {%1, %2, %3, %4};"
                     :: "r"(s_hi + off), "r"(a.x), "r"(a.y), "r"(a.z), "r"(a.w));
        asm volatile("st.shared.v4.b32 [%0], {%1, %2, %3, %4};"
                     :: "r"(s_lo + off), "r"(b.x), "r"(b.y), "r"(b.z), "r"(b.w));
    }
}

// ---------------------------------------------------------------------------
// bf16-split tensor-core GEMM: C[128,128] = A[M,K] * B[N,K]^T  (both K-major)
// 4 warps (warp tile 64x64), 128 threads, 2 CTAs/SM. R9-proven mainloop.
// MODE 0: X @ W^T  -> scatter to g_Q / g_K / g_Vt(transposed)   [R9-identical]
// MODE 1: Q @ K^T * scale -> g_S   (per batch)                  [R9-identical]
// MODE 2: P @ Vt^T -> out   (A = pre-split Ph/Pl; B = fp32 in-loop split)
// ---------------------------------------------------------------------------
template <int MODE>
__global__ __launch_bounds__(128) void mma_gemm(const float* __restrict__ X,
                                                const float* __restrict__ W,
                                                float* __restrict__ Out) {
    extern __shared__ char smem[];
    const uint32_t sm = smem_u32(smem);
    const int t = threadIdx.x;
    const int wid = t >> 5;
    const int l = t & 31;
    const int z = blockIdx.z;

    const float* A = nullptr;
    const float* B = nullptr;
    const bf16 *Ahi = nullptr, *Alo = nullptr;
    float* C = nullptr;
    int K;
    if (MODE == 0) { A = X; B = W; K = DIM; }
    else if (MODE == 1) {
        A = g_Q + (size_t)z * SEQ * DIM;
        B = g_K + (size_t)z * SEQ * DIM;
        C = g_S + (size_t)z * SEQ * SEQ;
        K = DIM;
    } else {
        Ahi = g_Ph + (size_t)z * SEQ * SEQ;
        Alo = g_Pl + (size_t)z * SEQ * SEQ;
        B = g_Vt + (size_t)z * DIM * SEQ;
        C = Out  + (size_t)z * SEQ * DIM;
        K = SEQ;
    }

    const int row0 = blockIdx.y * 128;
    const int col0 = blockIdx.x * 128;
    const int KI = K / 32;

    const int wm = (wid >> 1) * 64;     // warp M offset (2x2 warp grid)
    const int wn = (wid & 1) * 64;      // warp N offset (64-wide)

    const int a_row = l & 15;
    const int a_koff = ((l >> 4) & 1) * 8;
    const int b_row = (l & 7) + ((l >> 4) & 1) * 8;
    const int b_koff = ((l >> 3) & 1) * 8;

    float acc[4][8][4];                 // 128 regs
#pragma unroll
    for (int mi = 0; mi < 4; mi++)
#pragma unroll
        for (int ni = 0; ni < 8; ni++)
#pragma unroll
            for (int j = 0; j < 4; j++) acc[mi][ni][j] = 0.0f;

    float4 pf[8];                       // half-stage prefetch buffer (32 regs)
    uint4* pfb = (uint4*)pf;            // bf16-path view (mode 2 A operand)

    // prologue: stage 0 (A then B halves)
    if (MODE == 2) {
        half_load_b(pfb, Ahi, Alo, K, row0, 0, t);
        half_store_b(pfb, sm, sm + MAT_BYTES, t);
    } else {
        half_load(pf, A, K, row0, 0, t);
        half_store(pf, sm, sm + MAT_BYTES, t);
    }
    half_load(pf, B, K, col0, 0, t);
    half_store(pf, sm + 2 * MAT_BYTES, sm + 3 * MAT_BYTES, t);
    __syncthreads();

    for (int it = 0; it < KI; it++) {
        const int s = it & 1;
        const uint32_t stg = sm + s * STAGE_BYTES;
        const uint32_t nstg = sm + (1 - s) * STAGE_BYTES;
        const bool pfv = (it + 1 < KI);
        const int kb = (it + 1) * 32;

        // prefetch A-half for next iter (LDG latency covered by k0=0 compute)
        if (pfv) {
            if (MODE == 2) half_load_b(pfb, Ahi, Alo, K, row0, kb, t);
            else           half_load(pf, A, K, row0, kb, t);
        }

        const uint32_t sAh = stg;
        const uint32_t sAl = stg + MAT_BYTES;
        const uint32_t sBh = stg + 2 * MAT_BYTES;
        const uint32_t sBl = stg + 3 * MAT_BYTES;

#pragma unroll
        for (int k0 = 0; k0 < 32; k0 += 16) {
            uint32_t bH[8][2], bL[8][2];
#pragma unroll
            for (int nb = 0; nb < 4; nb++) {
                const uint32_t off =
                    (uint32_t)((wn + nb * 16 + b_row) * ROWB + (k0 + b_koff) * 2);
                uint32_t r0, r1, r2, r3;
                ldm4(sBh + off, r0, r1, r2, r3);
                bH[2 * nb][0] = r0; bH[2 * nb][1] = r1;
                bH[2 * nb + 1][0] = r2; bH[2 * nb + 1][1] = r3;
                ldm4(sBl + off, r0, r1, r2, r3);
                bL[2 * nb][0] = r0; bL[2 * nb][1] = r1;
                bL[2 * nb + 1][0] = r2; bL[2 * nb + 1][1] = r3;
            }
#pragma unroll
            for (int mi = 0; mi < 4; mi++) {
                uint32_t aH[4], aL[4];
                const uint32_t off =
                    (uint32_t)((wm + mi * 16 + a_row) * ROWB + (k0 + a_koff) * 2);
                ldm4(sAh + off, aH[0], aH[1], aH[2], aH[3]);
                ldm4(sAl + off, aL[0], aL[1], aL[2], aL[3]);
#pragma unroll
                for (int ni = 0; ni < 8; ni++) {
                    mma16816(acc[mi][ni], aH, bH[ni]);
                    mma16816(acc[mi][ni], aH, bL[ni]);
                    mma16816(acc[mi][ni], aL, bH[ni]);
                }
            }

            // between the two k0 steps: store A-half, start B-half prefetch
            if (k0 == 0 && pfv) {
                if (MODE == 2) half_store_b(pfb, nstg, nstg + MAT_BYTES, t);
                else           half_store(pf, nstg, nstg + MAT_BYTES, t);
                half_load(pf, B, K, col0, kb, t);
            }
        }

        if (pfv) half_store(pf, nstg + 2 * MAT_BYTES, nstg + 3 * MAT_BYTES, t);
        __syncthreads();
    }

    // Epilogue: fragments -> padded smem -> (scatter) gmem
    float* Csh = (float*)smem;                     // 128 x 130 fp32 (66.6 KB)
#pragma unroll
    for (int mi = 0; mi < 4; mi++)
#pragma unroll
        for (int ni = 0; ni < 8; ni++) {
            const int r = wm + mi * 16 + (l >> 2);
            const int c = wn + ni * 8 + (l & 3) * 2;
            float d0 = acc[mi][ni][0], d1 = acc[mi][ni][1];
            float d2 = acc[mi][ni][2], d3 = acc[mi][ni][3];
            if (MODE == 1) { d0 *= SCALE; d1 *= SCALE; d2 *= SCALE; d3 *= SCALE; }
            Csh[r * 130 + c]           = d0;
            Csh[r * 130 + c + 1]       = d1;
            Csh[(r + 8) * 130 + c]     = d2;
            Csh[(r + 8) * 130 + c + 1] = d3;
        }
    __syncthreads();

    for (int i = t; i < 128 * 128; i += 128) {
        const int r = i >> 7, c = i & 127;
        const float v = Csh[r * 130 + c];
        if (MODE == 0) {
            const int grow = row0 + r;
            const int col = col0 + c;
            const int which = col % 3;             // qkv reshape (d,3)
            const int oc = col / 3;
            if (which == 0)      g_Q[(size_t)grow * DIM + oc] = v;
            else if (which == 1) g_K[(size_t)grow * DIM + oc] = v;
            else {
                const int b = grow >> 11, tt = grow & 2047;
                g_Vt[((size_t)b * DIM + oc) * SEQ + tt] = v;
            }
        } else if (MODE == 1) {
            C[(size_t)(row0 + r) * SEQ + col0 + c] = v;
        } else {
            C[(size_t)(row0 + r) * DIM + col0 + c] = v;
        }
    }
}

// ---------------------------------------------------------------------------
// Row softmax: g_S row (2048 fp32) -> Ph/Pl bf16. 8 consecutive per thread.
// ---------------------------------------------------------------------------
__global__ __launch_bounds__(256) void softmax_k() {
    const size_t base = (size_t)blockIdx.x * SEQ;
    const float* p = g_S + base;
    const int t = threadIdx.x;
    const int lane = t & 31;
    const int warp = t >> 5;
    __shared__ float red[2][8];

    const float4 a = *(const float4*)(p + t * 8);
    const float4 b = *(const float4*)(p + t * 8 + 4);
    float v[8] = {a.x, a.y, a.z, a.w, b.x, b.y, b.z, b.w};

    float m = -1e30f;
#pragma unroll
    for (int i = 0; i < 8; i++) m = fmaxf(m, v[i]);
#pragma unroll
    for (int off = 16; off > 0; off >>= 1)
        m = fmaxf(m, __shfl_xor_sync(0xffffffffu, m, off));
    if (lane == 0) red[0][warp] = m;
    __syncthreads();
    m = red[0][0];
#pragma unroll
    for (int w = 1; w < 8; w++) m = fmaxf(m, red[0][w]);

    float s = 0.0f;
#pragma unroll
    for (int i = 0; i < 8; i++) { v[i] = __expf(v[i] - m); s += v[i]; }
#pragma unroll
    for (int off = 16; off > 0; off >>= 1)
        s += __shfl_xor_sync(0xffffffffu, s, off);
    if (lane == 0) red[1][warp] = s;
    __syncthreads();
    s = red[1][0];
#pragma unroll
    for (int w = 1; w < 8; w++) s += red[1][w];

    const float inv = 1.0f / s;
    bf16 h[8], lo[8];
#pragma unroll
    for (int i = 0; i < 8; i++) {
        const float q = v[i] * inv;
        h[i] = __float2bfloat16(q);
        lo[i] = __float2bfloat16(q - __bfloat162float(h[i]));
    }
    *(uint4*)(g_Ph + base + t * 8) = *(const uint4*)h;
    *(uint4*)(g_Pl + base + t * 8) = *(const uint4*)lo;
}

// ---------------------------------------------------------------------------
extern "C" void kernel_launch(void* const* d_in, const int* in_sizes, int n_in,
                              void* d_out, int out_size) {
    const float* x = (const float*)d_in[0];    // [4, 2048, 1024]
    const float* W = (const float*)d_in[1];    // [3072, 1024]
    float* out = (float*)d_out;                // [4, 2048, 1024]

    cudaFuncSetAttribute(mma_gemm<0>, cudaFuncAttributeMaxDynamicSharedMemorySize, SMEM_BYTES);
    cudaFuncSetAttribute(mma_gemm<1>, cudaFuncAttributeMaxDynamicSharedMemorySize, SMEM_BYTES);
    cudaFuncSetAttribute(mma_gemm<2>, cudaFuncAttributeMaxDynamicSharedMemorySize, SMEM_BYTES);

    // 1) QKV projection (scatter epilogue de-interleaves into Q / K / V^T)
    mma_gemm<0><<<dim3(NQKV / 128, (BATCH * SEQ) / 128, 1), 128, SMEM_BYTES>>>(x, W, nullptr);
    // 2) scores = Q K^T * scale
    mma_gemm<1><<<dim3(SEQ / 128, SEQ / 128, BATCH), 128, SMEM_BYTES>>>(nullptr, nullptr, nullptr);
    // 3) softmax -> P hi/lo (pre-split "for free" — same bytes written)
    softmax_k<<<dim3(BATCH * SEQ), 256>>>();
    // 4) out = P V  (A staging is pure copy)
    mma_gemm<2><<<dim3(DIM / 128, SEQ / 128, BATCH), 128, SMEM_BYTES>>>(nullptr, nullptr, out);
}

// round 15
// speedup vs baseline: 1.3793x; 1.3368x over previous
#include <cuda_runtime.h>
#include <cuda_fp16.h>
#include <cstdint>
#include <cstddef>

#define BATCH 4
#define SEQ   2048
#define DIM   1024
#define NQKV  3072
#define SCALE 0.03125f   // 1024^-0.5

// Scratch (static device globals — allocation-free per harness rules)
__device__ float g_Q [(size_t)BATCH * SEQ * DIM];   // [b*t, d]
__device__ float g_K [(size_t)BATCH * SEQ * DIM];   // [b*t, d]
__device__ float g_Vt[(size_t)BATCH * DIM * SEQ];   // [b, d, t] (transposed V)
__device__ float g_S [(size_t)BATCH * SEQ * SEQ];   // [b, t, t]

// ---------------------------------------------------------------------------
// helpers
// ---------------------------------------------------------------------------
__device__ __forceinline__ uint32_t smem_u32(const void* p) {
    uint32_t a;
    asm("{ .reg .u64 t; cvta.to.shared.u64 t, %1; cvt.u32.u64 %0, t; }"
        : "=r"(a) : "l"(p));
    return a;
}

__device__ __forceinline__ void ldm4(uint32_t addr, uint32_t& r0, uint32_t& r1,
                                     uint32_t& r2, uint32_t& r3) {
    asm volatile("ldmatrix.sync.aligned.m8n8.x4.shared.b16 {%0,%1,%2,%3}, [%4];"
                 : "=r"(r0), "=r"(r1), "=r"(r2), "=r"(r3) : "r"(addr));
}

__device__ __forceinline__ void mma16816(float* d, const uint32_t* a, const uint32_t* b) {
    asm volatile(
        "mma.sync.aligned.m16n8k16.row.col.f32.f16.f16.f32 "
        "{%0,%1,%2,%3}, {%4,%5,%6,%7}, {%8,%9}, {%0,%1,%2,%3};"
        : "+f"(d[0]), "+f"(d[1]), "+f"(d[2]), "+f"(d[3])
        : "r"(a[0]), "r"(a[1]), "r"(a[2]), "r"(a[3]), "r"(b[0]), "r"(b[1]));
}

// smem geometry: rows padded to 40 fp16 (80B) — conflict-free for ldmatrix
#define ROWB        80
#define MAT_BYTES   (128 * ROWB)                 // 10240 B (128 x 32 fp16 tile)
#define STAGE_BYTES (3 * MAT_BYTES)              // Ah | Bh | Bl = 30720 B
#define SMEM_BYTES  66560                        // max(2 stages, 128x130 fp32 epi)

// ---------------------------------------------------------------------------
// fp32 half-stage staging: one 128x32 fp32 tile = 8 x 16B chunks per thread.
// fidx = t + i*128, r = fidx>>3, c = fidx&7 (coalesced, 8 thr per 128B row).
// ---------------------------------------------------------------------------
__device__ __forceinline__ void half_load(float4* v, const float* __restrict__ M,
                                          int K, int row0, int kb, int t) {
#pragma unroll
    for (int i = 0; i < 8; i++) {
        const int fidx = t + i * 128;
        const int r = fidx >> 3, c = fidx & 7;
        v[i] = *(const float4*)(M + (size_t)(row0 + r) * K + kb + c * 4);
    }
}

// fp16 hi+lo split store of one float4 chunk (B operand)
__device__ __forceinline__ void cvt_st_hl(const float4 v, uint32_t s_hi, uint32_t s_lo,
                                          uint32_t off) {
    const __half2 h01 = __floats2half2_rn(v.x, v.y);
    const __half2 h23 = __floats2half2_rn(v.z, v.w);
    const float2 f01 = __half22float2(h01);
    const float2 f23 = __half22float2(h23);
    const __half2 l01 = __floats2half2_rn(v.x - f01.x, v.y - f01.y);
    const __half2 l23 = __floats2half2_rn(v.z - f23.x, v.w - f23.y);
    const uint32_t h0 = *(const uint32_t*)&h01;
    const uint32_t h1 = *(const uint32_t*)&h23;
    const uint32_t l0 = *(const uint32_t*)&l01;
    const uint32_t l1 = *(const uint32_t*)&l23;
    asm volatile("st.shared.v2.u32 [%0], {%1, %2};" :: "r"(s_hi + off), "r"(h0), "r"(h1));
    asm volatile("st.shared.v2.u32 [%0], {%1, %2};" :: "r"(s_lo + off), "r"(l0), "r"(l1));
}

// fp16 hi-only store of one float4 chunk (A operand)
__device__ __forceinline__ void cvt_st_h(const float4 v, uint32_t s_hi, uint32_t off) {
    const __half2 h01 = __floats2half2_rn(v.x, v.y);
    const __half2 h23 = __floats2half2_rn(v.z, v.w);
    const uint32_t h0 = *(const uint32_t*)&h01;
    const uint32_t h1 = *(const uint32_t*)&h23;
    asm volatile("st.shared.v2.u32 [%0], {%1, %2};" :: "r"(s_hi + off), "r"(h0), "r"(h1));
}

__device__ __forceinline__ void half_store_A(const float4* v, uint32_t s_hi, int t) {
#pragma unroll
    for (int i = 0; i < 8; i++) {
        const int fidx = t + i * 128;
        const int r = fidx >> 3, c = fidx & 7;
        cvt_st_h(v[i], s_hi, (uint32_t)(r * ROWB + c * 8));
    }
}

__device__ __forceinline__ void half_store_B(const float4* v, uint32_t s_hi,
                                             uint32_t s_lo, int t) {
#pragma unroll
    for (int i = 0; i < 8; i++) {
        const int fidx = t + i * 128;
        const int r = fidx >> 3, c = fidx & 7;
        cvt_st_hl(v[i], s_hi, s_lo, (uint32_t)(r * ROWB + c * 8));
    }
}

// ---------------------------------------------------------------------------
// fp16 2-term split GEMM: C = A*B^T with A ~ Ah, B ~ Bh + Bl.
// acc += Ah*Bh + Ah*Bl  (dropped Al*B term ~2^-12 relative).
// 4 warps (warp tile 64x64), 128 threads, 2 CTAs/SM. R9-proven mainloop.
// MODE 0: X @ W^T  -> scatter to g_Q / g_K / g_Vt(transposed)
// MODE 1: Q @ K^T * scale -> g_S   (per batch)
// MODE 2: P @ Vt^T -> out          (per batch)
// ---------------------------------------------------------------------------
template <int MODE>
__global__ __launch_bounds__(128) void mma_gemm(const float* __restrict__ X,
                                                const float* __restrict__ W,
                                                float* __restrict__ Out) {
    extern __shared__ char smem[];
    const uint32_t sm = smem_u32(smem);
    const int t = threadIdx.x;
    const int wid = t >> 5;
    const int l = t & 31;
    const int z = blockIdx.z;

    const float* A;
    const float* B;
    float* C = nullptr;
    int K;
    if (MODE == 0) { A = X; B = W; K = DIM; }
    else if (MODE == 1) {
        A = g_Q + (size_t)z * SEQ * DIM;
        B = g_K + (size_t)z * SEQ * DIM;
        C = g_S + (size_t)z * SEQ * SEQ;
        K = DIM;
    } else {
        A = g_S  + (size_t)z * SEQ * SEQ;
        B = g_Vt + (size_t)z * DIM * SEQ;
        C = Out  + (size_t)z * SEQ * DIM;
        K = SEQ;
    }

    const int row0 = blockIdx.y * 128;
    const int col0 = blockIdx.x * 128;
    const int KI = K / 32;

    const int wm = (wid >> 1) * 64;     // warp M offset (2x2 warp grid)
    const int wn = (wid & 1) * 64;      // warp N offset (64-wide)

    const int a_row = l & 15;
    const int a_koff = ((l >> 4) & 1) * 8;
    const int b_row = (l & 7) + ((l >> 4) & 1) * 8;
    const int b_koff = ((l >> 3) & 1) * 8;

    float acc[4][8][4];                 // 128 regs
#pragma unroll
    for (int mi = 0; mi < 4; mi++)
#pragma unroll
        for (int ni = 0; ni < 8; ni++)
#pragma unroll
            for (int j = 0; j < 4; j++) acc[mi][ni][j] = 0.0f;

    float4 pf[8];                       // half-stage prefetch buffer

    // prologue: stage 0 (A then B halves)
    half_load(pf, A, K, row0, 0, t);
    half_store_A(pf, sm, t);
    half_load(pf, B, K, col0, 0, t);
    half_store_B(pf, sm + MAT_BYTES, sm + 2 * MAT_BYTES, t);
    __syncthreads();

    for (int it = 0; it < KI; it++) {
        const int s = it & 1;
        const uint32_t stg = sm + s * STAGE_BYTES;
        const uint32_t nstg = sm + (1 - s) * STAGE_BYTES;
        const bool pfv = (it + 1 < KI);
        const int kb = (it + 1) * 32;

        // prefetch A-half for next iter (LDG latency covered by k0=0 compute)
        if (pfv) half_load(pf, A, K, row0, kb, t);

        const uint32_t sAh = stg;
        const uint32_t sBh = stg + MAT_BYTES;
        const uint32_t sBl = stg + 2 * MAT_BYTES;

#pragma unroll
        for (int k0 = 0; k0 < 32; k0 += 16) {
            uint32_t bH[8][2], bL[8][2];
#pragma unroll
            for (int nb = 0; nb < 4; nb++) {
                const uint32_t off =
                    (uint32_t)((wn + nb * 16 + b_row) * ROWB + (k0 + b_koff) * 2);
                uint32_t r0, r1, r2, r3;
                ldm4(sBh + off, r0, r1, r2, r3);
                bH[2 * nb][0] = r0; bH[2 * nb][1] = r1;
                bH[2 * nb + 1][0] = r2; bH[2 * nb + 1][1] = r3;
                ldm4(sBl + off, r0, r1, r2, r3);
                bL[2 * nb][0] = r0; bL[2 * nb][1] = r1;
                bL[2 * nb + 1][0] = r2; bL[2 * nb + 1][1] = r3;
            }
#pragma unroll
            for (int mi = 0; mi < 4; mi++) {
                uint32_t aH[4];
                const uint32_t off =
                    (uint32_t)((wm + mi * 16 + a_row) * ROWB + (k0 + a_koff) * 2);
                ldm4(sAh + off, aH[0], aH[1], aH[2], aH[3]);
#pragma unroll
                for (int ni = 0; ni < 8; ni++) mma16816(acc[mi][ni], aH, bH[ni]);
#pragma unroll
                for (int ni = 0; ni < 8; ni++) mma16816(acc[mi][ni], aH, bL[ni]);
            }

            // between the two k0 steps: store A-half, start B-half prefetch
            if (k0 == 0 && pfv) {
                half_store_A(pf, nstg, t);
                half_load(pf, B, K, col0, kb, t);
            }
        }

        if (pfv) half_store_B(pf, nstg + MAT_BYTES, nstg + 2 * MAT_BYTES, t);
        __syncthreads();
    }

    // Epilogue: fragments -> padded smem -> (scatter) gmem
    float* Csh = (float*)smem;                     // 128 x 130 fp32 (66.6 KB)
#pragma unroll
    for (int mi = 0; mi < 4; mi++)
#pragma unroll
        for (int ni = 0; ni < 8; ni++) {
            const int r = wm + mi * 16 + (l >> 2);
            const int c = wn + ni * 8 + (l & 3) * 2;
            float d0 = acc[mi][ni][0], d1 = acc[mi][ni][1];
            float d2 = acc[mi][ni][2], d3 = acc[mi][ni][3];
            if (MODE == 1) { d0 *= SCALE; d1 *= SCALE; d2 *= SCALE; d3 *= SCALE; }
            Csh[r * 130 + c]           = d0;
            Csh[r * 130 + c + 1]       = d1;
            Csh[(r + 8) * 130 + c]     = d2;
            Csh[(r + 8) * 130 + c + 1] = d3;
        }
    __syncthreads();

    for (int i = t; i < 128 * 128; i += 128) {
        const int r = i >> 7, c = i & 127;
        const float v = Csh[r * 130 + c];
        if (MODE == 0) {
            const int grow = row0 + r;
            const int col = col0 + c;
            const int which = col % 3;             // qkv reshape (d,3)
            const int oc = col / 3;
            if (which == 0)      g_Q[(size_t)grow * DIM + oc] = v;
            else if (which == 1) g_K[(size_t)grow * DIM + oc] = v;
            else {
                const int b = grow >> 11, tt = grow & 2047;
                g_Vt[((size_t)b * DIM + oc) * SEQ + tt] = v;
            }
        } else if (MODE == 1) {
            C[(size_t)(row0 + r) * SEQ + col0 + c] = v;
        } else {
            C[(size_t)(row0 + r) * DIM + col0 + c] = v;
        }
    }
}

// ---------------------------------------------------------------------------
// Row softmax over g_S: one block (256 threads) per row of length 2048.
// ---------------------------------------------------------------------------
__global__ __launch_bounds__(256) void softmax_k() {
    float* p = g_S + (size_t)blockIdx.x * SEQ;
    const int t = threadIdx.x;
    const int lane = t & 31;
    const int warp = t >> 5;
    __shared__ float red[2][8];

    float v[8];
    float m = -1e30f;
#pragma unroll
    for (int i = 0; i < 8; i++) { v[i] = p[t + i * 256]; m = fmaxf(m, v[i]); }
#pragma unroll
    for (int off = 16; off > 0; off >>= 1)
        m = fmaxf(m, __shfl_xor_sync(0xffffffffu, m, off));
    if (lane == 0) red[0][warp] = m;
    __syncthreads();
    m = red[0][0];
#pragma unroll
    for (int w = 1; w < 8; w++) m = fmaxf(m, red[0][w]);

    float s = 0.0f;
#pragma unroll
    for (int i = 0; i < 8; i++) { v[i] = __expf(v[i] - m); s += v[i]; }
#pragma unroll
    for (int off = 16; off > 0; off >>= 1)
        s += __shfl_xor_sync(0xffffffffu, s, off);
    if (lane == 0) red[1][warp] = s;
    __syncthreads();
    s = red[1][0];
#pragma unroll
    for (int w = 1; w < 8; w++) s += red[1][w];

    const float inv = 1.0f / s;
#pragma unroll
    for (int i = 0; i < 8; i++) p[t + i * 256] = v[i] * inv;
}

// ---------------------------------------------------------------------------
extern "C" void kernel_launch(void* const* d_in, const int* in_sizes, int n_in,
                              void* d_out, int out_size) {
    const float* x = (const float*)d_in[0];    // [4, 2048, 1024]
    const float* W = (const float*)d_in[1];    // [3072, 1024]
    float* out = (float*)d_out;                // [4, 2048, 1024]

    cudaFuncSetAttribute(mma_gemm<0>, cudaFuncAttributeMaxDynamicSharedMemorySize, SMEM_BYTES);
    cudaFuncSetAttribute(mma_gemm<1>, cudaFuncAttributeMaxDynamicSharedMemorySize, SMEM_BYTES);
    cudaFuncSetAttribute(mma_gemm<2>, cudaFuncAttributeMaxDynamicSharedMemorySize, SMEM_BYTES);

    // 1) QKV projection (scatter epilogue de-interleaves into Q / K / V^T)
    mma_gemm<0><<<dim3(NQKV / 128, (BATCH * SEQ) / 128, 1), 128, SMEM_BYTES>>>(x, W, nullptr);
    // 2) scores = Q K^T * scale
    mma_gemm<1><<<dim3(SEQ / 128, SEQ / 128, BATCH), 128, SMEM_BYTES>>>(nullptr, nullptr, nullptr);
    // 3) row softmax
    softmax_k<<<dim3(BATCH * SEQ), 256>>>();
    // 4) out = P V
    mma_gemm<2><<<dim3(DIM / 128, SEQ / 128, BATCH), 128, SMEM_BYTES>>>(nullptr, nullptr, out);
}

// round 16
// speedup vs baseline: 1.4307x; 1.0373x over previous
#include <cuda_runtime.h>
#include <cuda_fp16.h>
#include <cstdint>
#include <cstddef>

#define BATCH 4
#define SEQ   2048
#define DIM   1024
#define NQKV  3072
#define SCALE 0.03125f   // 1024^-0.5

// Scratch (static device globals — allocation-free per harness rules)
__device__ __half g_Qh[(size_t)BATCH * SEQ * DIM];  // fp16 Q (A-operand, hi only)
__device__ float  g_K [(size_t)BATCH * SEQ * DIM];  // [b*t, d]
__device__ float  g_Vt[(size_t)BATCH * DIM * SEQ];  // [b, d, t] (transposed V)
__device__ float  g_S [(size_t)BATCH * SEQ * SEQ];  // [b, t, t] scores fp32
__device__ __half g_P [(size_t)BATCH * SEQ * SEQ];  // fp16 probs (A-operand)

// ---------------------------------------------------------------------------
// helpers
// ---------------------------------------------------------------------------
__device__ __forceinline__ uint32_t smem_u32(const void* p) {
    uint32_t a;
    asm("{ .reg .u64 t; cvta.to.shared.u64 t, %1; cvt.u32.u64 %0, t; }"
        : "=r"(a) : "l"(p));
    return a;
}

__device__ __forceinline__ void ldm4(uint32_t addr, uint32_t& r0, uint32_t& r1,
                                     uint32_t& r2, uint32_t& r3) {
    asm volatile("ldmatrix.sync.aligned.m8n8.x4.shared.b16 {%0,%1,%2,%3}, [%4];"
                 : "=r"(r0), "=r"(r1), "=r"(r2), "=r"(r3) : "r"(addr));
}

__device__ __forceinline__ void mma16816(float* d, const uint32_t* a, const uint32_t* b) {
    asm volatile(
        "mma.sync.aligned.m16n8k16.row.col.f32.f16.f16.f32 "
        "{%0,%1,%2,%3}, {%4,%5,%6,%7}, {%8,%9}, {%0,%1,%2,%3};"
        : "+f"(d[0]), "+f"(d[1]), "+f"(d[2]), "+f"(d[3])
        : "r"(a[0]), "r"(a[1]), "r"(a[2]), "r"(a[3]), "r"(b[0]), "r"(b[1]));
}

// smem geometry: rows padded to 40 fp16 (80B) — conflict-free for ldmatrix
#define ROWB        80
#define MAT_BYTES   (128 * ROWB)                 // 10240 B (128 x 32 fp16 tile)
#define STAGE_BYTES (3 * MAT_BYTES)              // Ah | Bh | Bl = 30720 B
#define SMEM_BYTES  66560                        // max(2 stages, 128x130 fp32 epi)

// ---------------------------------------------------------------------------
// fp32 half-stage staging (one 128x32 fp32 tile = 8 x 16B chunks / thread).
// fidx = t + i*128, r = fidx>>3, c = fidx&7 (coalesced, 8 thr per 128B row).
// ---------------------------------------------------------------------------
__device__ __forceinline__ void half_load(float4* v, const float* __restrict__ M,
                                          int K, int row0, int kb, int t) {
#pragma unroll
    for (int i = 0; i < 8; i++) {
        const int fidx = t + i * 128;
        const int r = fidx >> 3, c = fidx & 7;
        v[i] = *(const float4*)(M + (size_t)(row0 + r) * K + kb + c * 4);
    }
}

// fp16 hi+lo split store of one float4 chunk (B operand)
__device__ __forceinline__ void cvt_st_hl(const float4 v, uint32_t s_hi, uint32_t s_lo,
                                          uint32_t off) {
    const __half2 h01 = __floats2half2_rn(v.x, v.y);
    const __half2 h23 = __floats2half2_rn(v.z, v.w);
    const float2 f01 = __half22float2(h01);
    const float2 f23 = __half22float2(h23);
    const __half2 l01 = __floats2half2_rn(v.x - f01.x, v.y - f01.y);
    const __half2 l23 = __floats2half2_rn(v.z - f23.x, v.w - f23.y);
    const uint32_t h0 = *(const uint32_t*)&h01;
    const uint32_t h1 = *(const uint32_t*)&h23;
    const uint32_t l0 = *(const uint32_t*)&l01;
    const uint32_t l1 = *(const uint32_t*)&l23;
    asm volatile("st.shared.v2.u32 [%0], {%1, %2};" :: "r"(s_hi + off), "r"(h0), "r"(h1));
    asm volatile("st.shared.v2.u32 [%0], {%1, %2};" :: "r"(s_lo + off), "r"(l0), "r"(l1));
}

// fp16 hi-only store of one float4 chunk (A operand, MODE 0)
__device__ __forceinline__ void cvt_st_h(const float4 v, uint32_t s_hi, uint32_t off) {
    const __half2 h01 = __floats2half2_rn(v.x, v.y);
    const __half2 h23 = __floats2half2_rn(v.z, v.w);
    const uint32_t h0 = *(const uint32_t*)&h01;
    const uint32_t h1 = *(const uint32_t*)&h23;
    asm volatile("st.shared.v2.u32 [%0], {%1, %2};" :: "r"(s_hi + off), "r"(h0), "r"(h1));
}

__device__ __forceinline__ void half_store_A32(const float4* v, uint32_t s_hi, int t) {
#pragma unroll
    for (int i = 0; i < 8; i++) {
        const int fidx = t + i * 128;
        const int r = fidx >> 3, c = fidx & 7;
        cvt_st_h(v[i], s_hi, (uint32_t)(r * ROWB + c * 8));
    }
}

__device__ __forceinline__ void half_store_B(const float4* v, uint32_t s_hi,
                                             uint32_t s_lo, int t) {
#pragma unroll
    for (int i = 0; i < 8; i++) {
        const int fidx = t + i * 128;
        const int r = fidx >> 3, c = fidx & 7;
        cvt_st_hl(v[i], s_hi, s_lo, (uint32_t)(r * ROWB + c * 8));
    }
}

// ---------------------------------------------------------------------------
// fp16 A-operand pure-copy staging (MODES 1,2): 128x32 fp16 tile = 8 KB,
// 4 x 16B chunks per thread. fidx = t + i*128, r = fidx>>2, c = fidx&3.
// ---------------------------------------------------------------------------
__device__ __forceinline__ void half_load_h(uint4* v, const __half* __restrict__ M,
                                            int K, int row0, int kb, int t) {
#pragma unroll
    for (int i = 0; i < 4; i++) {
        const int fidx = t + i * 128;
        const int r = fidx >> 2, c = fidx & 3;
        v[i] = *(const uint4*)(M + (size_t)(row0 + r) * K + kb + c * 8);
    }
}

__device__ __forceinline__ void half_store_h(const uint4* v, uint32_t s_hi, int t) {
#pragma unroll
    for (int i = 0; i < 4; i++) {
        const int fidx = t + i * 128;
        const int r = fidx >> 2, c = fidx & 3;
        const uint4 x = v[i];
        asm volatile("st.shared.v4.b32 [%0], {%1, %2, %3, %4};"
                     :: "r"(s_hi + (uint32_t)(r * ROWB + c * 16)),
                        "r"(x.x), "r"(x.y), "r"(x.z), "r"(x.w));
    }
}

// ---------------------------------------------------------------------------
// fp16 2-term split GEMM: C = A*B^T with A ~ Ah, B ~ Bh + Bl.
// acc += Ah*Bh + Ah*Bl.  4 warps (warp tile 64x64), 2 CTAs/SM.
// MODE 0: X @ W^T (A,B fp32)  -> Q(fp16) / K(fp32) / Vt(fp32) scatter
// MODE 1: Qh @ K^T * scale -> g_S     (A pre-converted fp16, pure copy)
// MODE 2: P @ Vt^T -> out             (A pre-converted fp16, pure copy)
// ---------------------------------------------------------------------------
template <int MODE>
__global__ __launch_bounds__(128) void mma_gemm(const float* __restrict__ X,
                                                const float* __restrict__ W,
                                                float* __restrict__ Out) {
    extern __shared__ char smem[];
    const uint32_t sm = smem_u32(smem);
    const int t = threadIdx.x;
    const int wid = t >> 5;
    const int l = t & 31;
    const int z = blockIdx.z;

    const float* A32 = nullptr;
    const __half* A16 = nullptr;
    const float* B;
    float* C = nullptr;
    int K;
    if (MODE == 0) { A32 = X; B = W; K = DIM; }
    else if (MODE == 1) {
        A16 = g_Qh + (size_t)z * SEQ * DIM;
        B = g_K + (size_t)z * SEQ * DIM;
        C = g_S + (size_t)z * SEQ * SEQ;
        K = DIM;
    } else {
        A16 = g_P + (size_t)z * SEQ * SEQ;
        B = g_Vt + (size_t)z * DIM * SEQ;
        C = Out  + (size_t)z * SEQ * DIM;
        K = SEQ;
    }

    const int row0 = blockIdx.y * 128;
    const int col0 = blockIdx.x * 128;
    const int KI = K / 32;

    const int wm = (wid >> 1) * 64;     // warp M offset (2x2 warp grid)
    const int wn = (wid & 1) * 64;      // warp N offset (64-wide)

    const int a_row = l & 15;
    const int a_koff = ((l >> 4) & 1) * 8;
    const int b_row = (l & 7) + ((l >> 4) & 1) * 8;
    const int b_koff = ((l >> 3) & 1) * 8;

    float acc[4][8][4];                 // 128 regs
#pragma unroll
    for (int mi = 0; mi < 4; mi++)
#pragma unroll
        for (int ni = 0; ni < 8; ni++)
#pragma unroll
            for (int j = 0; j < 4; j++) acc[mi][ni][j] = 0.0f;

    float4 pf[8];                       // half-stage prefetch buffer
    uint4* pfh = (uint4*)pf;            // fp16 A-path view (modes 1,2)

    // prologue: stage 0 (A then B halves)
    if (MODE == 0) {
        half_load(pf, A32, K, row0, 0, t);
        half_store_A32(pf, sm, t);
    } else {
        half_load_h(pfh, A16, K, row0, 0, t);
        half_store_h(pfh, sm, t);
    }
    half_load(pf, B, K, col0, 0, t);
    half_store_B(pf, sm + MAT_BYTES, sm + 2 * MAT_BYTES, t);
    __syncthreads();

    for (int it = 0; it < KI; it++) {
        const int s = it & 1;
        const uint32_t stg = sm + s * STAGE_BYTES;
        const uint32_t nstg = sm + (1 - s) * STAGE_BYTES;
        const bool pfv = (it + 1 < KI);
        const int kb = (it + 1) * 32;

        // prefetch A-half for next iter (LDG latency covered by k0=0 compute)
        if (pfv) {
            if (MODE == 0) half_load(pf, A32, K, row0, kb, t);
            else           half_load_h(pfh, A16, K, row0, kb, t);
        }

        const uint32_t sAh = stg;
        const uint32_t sBh = stg + MAT_BYTES;
        const uint32_t sBl = stg + 2 * MAT_BYTES;

#pragma unroll
        for (int k0 = 0; k0 < 32; k0 += 16) {
            uint32_t bH[8][2], bL[8][2];
#pragma unroll
            for (int nb = 0; nb < 4; nb++) {
                const uint32_t off =
                    (uint32_t)((wn + nb * 16 + b_row) * ROWB + (k0 + b_koff) * 2);
                uint32_t r0, r1, r2, r3;
                ldm4(sBh + off, r0, r1, r2, r3);
                bH[2 * nb][0] = r0; bH[2 * nb][1] = r1;
                bH[2 * nb + 1][0] = r2; bH[2 * nb + 1][1] = r3;
                ldm4(sBl + off, r0, r1, r2, r3);
                bL[2 * nb][0] = r0; bL[2 * nb][1] = r1;
                bL[2 * nb + 1][0] = r2; bL[2 * nb + 1][1] = r3;
            }
#pragma unroll
            for (int mi = 0; mi < 4; mi++) {
                uint32_t aH[4];
                const uint32_t off =
                    (uint32_t)((wm + mi * 16 + a_row) * ROWB + (k0 + a_koff) * 2);
                ldm4(sAh + off, aH[0], aH[1], aH[2], aH[3]);
#pragma unroll
                for (int ni = 0; ni < 8; ni++) mma16816(acc[mi][ni], aH, bH[ni]);
#pragma unroll
                for (int ni = 0; ni < 8; ni++) mma16816(acc[mi][ni], aH, bL[ni]);
            }

            // between the two k0 steps: store A-half, start B-half prefetch
            if (k0 == 0 && pfv) {
                if (MODE == 0) half_store_A32(pf, nstg, t);
                else           half_store_h(pfh, nstg, t);
                half_load(pf, B, K, col0, kb, t);
            }
        }

        if (pfv) half_store_B(pf, nstg + MAT_BYTES, nstg + 2 * MAT_BYTES, t);
        __syncthreads();
    }

    // Epilogue: fragments -> padded smem -> (scatter) gmem
    float* Csh = (float*)smem;                     // 128 x 130 fp32 (66.6 KB)
#pragma unroll
    for (int mi = 0; mi < 4; mi++)
#pragma unroll
        for (int ni = 0; ni < 8; ni++) {
            const int r = wm + mi * 16 + (l >> 2);
            const int c = wn + ni * 8 + (l & 3) * 2;
            float d0 = acc[mi][ni][0], d1 = acc[mi][ni][1];
            float d2 = acc[mi][ni][2], d3 = acc[mi][ni][3];
            if (MODE == 1) { d0 *= SCALE; d1 *= SCALE; d2 *= SCALE; d3 *= SCALE; }
            Csh[r * 130 + c]           = d0;
            Csh[r * 130 + c + 1]       = d1;
            Csh[(r + 8) * 130 + c]     = d2;
            Csh[(r + 8) * 130 + c + 1] = d3;
        }
    __syncthreads();

    for (int i = t; i < 128 * 128; i += 128) {
        const int r = i >> 7, c = i & 127;
        const float v = Csh[r * 130 + c];
        if (MODE == 0) {
            const int grow = row0 + r;
            const int col = col0 + c;
            const int which = col % 3;             // qkv reshape (d,3)
            const int oc = col / 3;
            if (which == 0)      g_Qh[(size_t)grow * DIM + oc] = __float2half_rn(v);
            else if (which == 1) g_K[(size_t)grow * DIM + oc] = v;
            else {
                const int b = grow >> 11, tt = grow & 2047;
                g_Vt[((size_t)b * DIM + oc) * SEQ + tt] = v;
            }
        } else if (MODE == 1) {
            C[(size_t)(row0 + r) * SEQ + col0 + c] = v;
        } else {
            C[(size_t)(row0 + r) * DIM + col0 + c] = v;
        }
    }
}

// ---------------------------------------------------------------------------
// Row softmax: g_S row (2048 fp32) -> g_P fp16. 8 consecutive per thread.
// ---------------------------------------------------------------------------
__global__ __launch_bounds__(256) void softmax_k() {
    const size_t base = (size_t)blockIdx.x * SEQ;
    const float* p = g_S + base;
    const int t = threadIdx.x;
    const int lane = t & 31;
    const int warp = t >> 5;
    __shared__ float red[2][8];

    const float4 a = *(const float4*)(p + t * 8);
    const float4 b = *(const float4*)(p + t * 8 + 4);
    float v[8] = {a.x, a.y, a.z, a.w, b.x, b.y, b.z, b.w};

    float m = -1e30f;
#pragma unroll
    for (int i = 0; i < 8; i++) m = fmaxf(m, v[i]);
#pragma unroll
    for (int off = 16; off > 0; off >>= 1)
        m = fmaxf(m, __shfl_xor_sync(0xffffffffu, m, off));
    if (lane == 0) red[0][warp] = m;
    __syncthreads();
    m = red[0][0];
#pragma unroll
    for (int w = 1; w < 8; w++) m = fmaxf(m, red[0][w]);

    float s = 0.0f;
#pragma unroll
    for (int i = 0; i < 8; i++) { v[i] = __expf(v[i] - m); s += v[i]; }
#pragma unroll
    for (int off = 16; off > 0; off >>= 1)
        s += __shfl_xor_sync(0xffffffffu, s, off);
    if (lane == 0) red[1][warp] = s;
    __syncthreads();
    s = red[1][0];
#pragma unroll
    for (int w = 1; w < 8; w++) s += red[1][w];

    const float inv = 1.0f / s;
    __half h[8];
#pragma unroll
    for (int i = 0; i < 8; i++) h[i] = __float2half_rn(v[i] * inv);
    *(uint4*)(g_P + base + t * 8) = *(const uint4*)h;
}

// ---------------------------------------------------------------------------
extern "C" void kernel_launch(void* const* d_in, const int* in_sizes, int n_in,
                              void* d_out, int out_size) {
    const float* x = (const float*)d_in[0];    // [4, 2048, 1024]
    const float* W = (const float*)d_in[1];    // [3072, 1024]
    float* out = (float*)d_out;                // [4, 2048, 1024]

    cudaFuncSetAttribute(mma_gemm<0>, cudaFuncAttributeMaxDynamicSharedMemorySize, SMEM_BYTES);
    cudaFuncSetAttribute(mma_gemm<1>, cudaFuncAttributeMaxDynamicSharedMemorySize, SMEM_BYTES);
    cudaFuncSetAttribute(mma_gemm<2>, cudaFuncAttributeMaxDynamicSharedMemorySize, SMEM_BYTES);

    // 1) QKV projection (Q emitted as fp16; K, V^T as fp32)
    mma_gemm<0><<<dim3(NQKV / 128, (BATCH * SEQ) / 128, 1), 128, SMEM_BYTES>>>(x, W, nullptr);
    // 2) scores = Q K^T * scale  (A pure-copy fp16)
    mma_gemm<1><<<dim3(SEQ / 128, SEQ / 128, BATCH), 128, SMEM_BYTES>>>(nullptr, nullptr, nullptr);
    // 3) row softmax -> fp16 P
    softmax_k<<<dim3(BATCH * SEQ), 256>>>();
    // 4) out = P V  (A pure-copy fp16)
    mma_gemm<2><<<dim3(DIM / 128, SEQ / 128, BATCH), 128, SMEM_BYTES>>>(nullptr, nullptr, out);
}

// round 17
// speedup vs baseline: 1.5975x; 1.1166x over previous
#include <cuda_runtime.h>
#include <cuda_fp16.h>
#include <cstdint>
#include <cstddef>

#define BATCH 4
#define SEQ   2048
#define DIM   1024
#define NQKV  3072
#define SCALE 0.03125f   // 1024^-0.5

// Scratch (static device globals — allocation-free per harness rules)
__device__ __half g_Q16[(size_t)BATCH * SEQ * DIM];  // fp16 Q  [b*t, d]
__device__ __half g_K16[(size_t)BATCH * SEQ * DIM];  // fp16 K  [b*t, d]
__device__ __half g_V16t[(size_t)BATCH * DIM * SEQ]; // fp16 V^T [b, d, t]
__device__ float  g_S [(size_t)BATCH * SEQ * SEQ];   // scores fp32
__device__ __half g_P [(size_t)BATCH * SEQ * SEQ];   // fp16 probs

// ---------------------------------------------------------------------------
// helpers
// ---------------------------------------------------------------------------
__device__ __forceinline__ uint32_t smem_u32(const void* p) {
    uint32_t a;
    asm("{ .reg .u64 t; cvta.to.shared.u64 t, %1; cvt.u32.u64 %0, t; }"
        : "=r"(a) : "l"(p));
    return a;
}

__device__ __forceinline__ void ldm4(uint32_t addr, uint32_t& r0, uint32_t& r1,
                                     uint32_t& r2, uint32_t& r3) {
    asm volatile("ldmatrix.sync.aligned.m8n8.x4.shared.b16 {%0,%1,%2,%3}, [%4];"
                 : "=r"(r0), "=r"(r1), "=r"(r2), "=r"(r3) : "r"(addr));
}

__device__ __forceinline__ void mma16816(float* d, const uint32_t* a, const uint32_t* b) {
    asm volatile(
        "mma.sync.aligned.m16n8k16.row.col.f32.f16.f16.f32 "
        "{%0,%1,%2,%3}, {%4,%5,%6,%7}, {%8,%9}, {%0,%1,%2,%3};"
        : "+f"(d[0]), "+f"(d[1]), "+f"(d[2]), "+f"(d[3])
        : "r"(a[0]), "r"(a[1]), "r"(a[2]), "r"(a[3]), "r"(b[0]), "r"(b[1]));
}

// smem geometry: rows padded to 40 fp16 (80B) — conflict-free for ldmatrix
#define ROWB        80
#define MAT_BYTES   (128 * ROWB)                 // 10240 B (128 x 32 fp16 tile)
#define SMEM_BYTES  66560                        // 128x130 fp32 epilogue bound

// ---------------------------------------------------------------------------
// fp32 half-stage staging (MODE 0): 8 x 16B chunks / thread; r=fidx>>3, c=fidx&7.
// ---------------------------------------------------------------------------
__device__ __forceinline__ void half_load(float4* v, const float* __restrict__ M,
                                          int K, int row0, int kb, int t) {
#pragma unroll
    for (int i = 0; i < 8; i++) {
        const int fidx = t + i * 128;
        const int r = fidx >> 3, c = fidx & 7;
        v[i] = *(const float4*)(M + (size_t)(row0 + r) * K + kb + c * 4);
    }
}

// fp16 hi+lo split store of one float4 chunk (W operand, MODE 0)
__device__ __forceinline__ void cvt_st_hl(const float4 v, uint32_t s_hi, uint32_t s_lo,
                                          uint32_t off) {
    const __half2 h01 = __floats2half2_rn(v.x, v.y);
    const __half2 h23 = __floats2half2_rn(v.z, v.w);
    const float2 f01 = __half22float2(h01);
    const float2 f23 = __half22float2(h23);
    const __half2 l01 = __floats2half2_rn(v.x - f01.x, v.y - f01.y);
    const __half2 l23 = __floats2half2_rn(v.z - f23.x, v.w - f23.y);
    const uint32_t h0 = *(const uint32_t*)&h01;
    const uint32_t h1 = *(const uint32_t*)&h23;
    const uint32_t l0 = *(const uint32_t*)&l01;
    const uint32_t l1 = *(const uint32_t*)&l23;
    asm volatile("st.shared.v2.u32 [%0], {%1, %2};" :: "r"(s_hi + off), "r"(h0), "r"(h1));
    asm volatile("st.shared.v2.u32 [%0], {%1, %2};" :: "r"(s_lo + off), "r"(l0), "r"(l1));
}

// fp16 hi-only store of one float4 chunk (X operand, MODE 0)
__device__ __forceinline__ void cvt_st_h(const float4 v, uint32_t s_hi, uint32_t off) {
    const __half2 h01 = __floats2half2_rn(v.x, v.y);
    const __half2 h23 = __floats2half2_rn(v.z, v.w);
    const uint32_t h0 = *(const uint32_t*)&h01;
    const uint32_t h1 = *(const uint32_t*)&h23;
    asm volatile("st.shared.v2.u32 [%0], {%1, %2};" :: "r"(s_hi + off), "r"(h0), "r"(h1));
}

__device__ __forceinline__ void half_store_A32(const float4* v, uint32_t s_hi, int t) {
#pragma unroll
    for (int i = 0; i < 8; i++) {
        const int fidx = t + i * 128;
        const int r = fidx >> 3, c = fidx & 7;
        cvt_st_h(v[i], s_hi, (uint32_t)(r * ROWB + c * 8));
    }
}

__device__ __forceinline__ void half_store_B32(const float4* v, uint32_t s_hi,
                                               uint32_t s_lo, int t) {
#pragma unroll
    for (int i = 0; i < 8; i++) {
        const int fidx = t + i * 128;
        const int r = fidx >> 3, c = fidx & 7;
        cvt_st_hl(v[i], s_hi, s_lo, (uint32_t)(r * ROWB + c * 8));
    }
}

// ---------------------------------------------------------------------------
// fp16 pure-copy staging (MODES 1,2): 128x32 fp16 tile = 8 KB, 4 x 16B
// chunks per thread. fidx = t + i*128, r = fidx>>2, c = fidx&3.
// ---------------------------------------------------------------------------
__device__ __forceinline__ void half_load_h(uint4* v, const __half* __restrict__ M,
                                            int K, int row0, int kb, int t) {
#pragma unroll
    for (int i = 0; i < 4; i++) {
        const int fidx = t + i * 128;
        const int r = fidx >> 2, c = fidx & 3;
        v[i] = *(const uint4*)(M + (size_t)(row0 + r) * K + kb + c * 8);
    }
}

__device__ __forceinline__ void half_store_h(const uint4* v, uint32_t s_dst, int t) {
#pragma unroll
    for (int i = 0; i < 4; i++) {
        const int fidx = t + i * 128;
        const int r = fidx >> 2, c = fidx & 3;
        const uint4 x = v[i];
        asm volatile("st.shared.v4.b32 [%0], {%1, %2, %3, %4};"
                     :: "r"(s_dst + (uint32_t)(r * ROWB + c * 16)),
                        "r"(x.x), "r"(x.y), "r"(x.z), "r"(x.w));
    }
}

// ---------------------------------------------------------------------------
// fp16 split GEMM, 4 warps (warp tile 64x64), 128 threads, 2 CTAs/SM.
// MODE 0: X @ W^T, A ~ fp16(X), B ~ Wh + Wl (2-term). Epilogue scatters
//         Q/K (fp16, [b*t,d]) and V^T (fp16, [b,d,t]).
// MODE 1: Q16 @ K16^T * scale -> g_S   (single-term, pure-copy staging)
// MODE 2: P @ V16t^T -> out            (single-term, pure-copy staging)
// ---------------------------------------------------------------------------
template <int MODE>
__global__ __launch_bounds__(128) void mma_gemm(const float* __restrict__ X,
                                                const float* __restrict__ W,
                                                float* __restrict__ Out) {
    extern __shared__ char smem[];
    const uint32_t sm = smem_u32(smem);
    const int t = threadIdx.x;
    const int wid = t >> 5;
    const int l = t & 31;
    const int z = blockIdx.z;

    constexpr int STB = (MODE == 0 ? 3 : 2) * MAT_BYTES;   // stage bytes

    const float* A32 = nullptr;
    const float* B32 = nullptr;
    const __half* A16 = nullptr;
    const __half* B16 = nullptr;
    float* C = nullptr;
    int K;
    if (MODE == 0) { A32 = X; B32 = W; K = DIM; }
    else if (MODE == 1) {
        A16 = g_Q16 + (size_t)z * SEQ * DIM;
        B16 = g_K16 + (size_t)z * SEQ * DIM;
        C = g_S + (size_t)z * SEQ * SEQ;
        K = DIM;
    } else {
        A16 = g_P + (size_t)z * SEQ * SEQ;
        B16 = g_V16t + (size_t)z * DIM * SEQ;
        C = Out + (size_t)z * SEQ * DIM;
        K = SEQ;
    }

    const int row0 = blockIdx.y * 128;
    const int col0 = blockIdx.x * 128;
    const int KI = K / 32;

    const int wm = (wid >> 1) * 64;     // warp M offset (2x2 warp grid)
    const int wn = (wid & 1) * 64;      // warp N offset (64-wide)

    const int a_row = l & 15;
    const int a_koff = ((l >> 4) & 1) * 8;
    const int b_row = (l & 7) + ((l >> 4) & 1) * 8;
    const int b_koff = ((l >> 3) & 1) * 8;

    float acc[4][8][4];                 // 128 regs
#pragma unroll
    for (int mi = 0; mi < 4; mi++)
#pragma unroll
        for (int ni = 0; ni < 8; ni++)
#pragma unroll
            for (int j = 0; j < 4; j++) acc[mi][ni][j] = 0.0f;

    float4 pf[8];                       // prefetch buffer (fp32 path)
    uint4* pfh = (uint4*)pf;            // fp16 path view: A in [0..3], B in [4..7]

    // prologue: stage 0
    if (MODE == 0) {
        half_load(pf, A32, K, row0, 0, t);
        half_store_A32(pf, sm, t);
        half_load(pf, B32, K, col0, 0, t);
        half_store_B32(pf, sm + MAT_BYTES, sm + 2 * MAT_BYTES, t);
    } else {
        half_load_h(pfh,     A16, K, row0, 0, t);
        half_load_h(pfh + 4, B16, K, col0, 0, t);
        half_store_h(pfh,     sm, t);
        half_store_h(pfh + 4, sm + MAT_BYTES, t);
    }
    __syncthreads();

    for (int it = 0; it < KI; it++) {
        const int s = it & 1;
        const uint32_t stg = sm + s * STB;
        const uint32_t nstg = sm + (1 - s) * STB;
        const bool pfv = (it + 1 < KI);
        const int kb = (it + 1) * 32;

        // prefetch A (and B for fp16 path) for next iter
        if (pfv) {
            if (MODE == 0) half_load(pf, A32, K, row0, kb, t);
            else {
                half_load_h(pfh,     A16, K, row0, kb, t);
                half_load_h(pfh + 4, B16, K, col0, kb, t);
            }
        }

        const uint32_t sAh = stg;
        const uint32_t sBh = stg + MAT_BYTES;
        const uint32_t sBl = stg + 2 * MAT_BYTES;   // mode 0 only

#pragma unroll
        for (int k0 = 0; k0 < 32; k0 += 16) {
            uint32_t bH[8][2], bL[8][2];
#pragma unroll
            for (int nb = 0; nb < 4; nb++) {
                const uint32_t off =
                    (uint32_t)((wn + nb * 16 + b_row) * ROWB + (k0 + b_koff) * 2);
                uint32_t r0, r1, r2, r3;
                ldm4(sBh + off, r0, r1, r2, r3);
                bH[2 * nb][0] = r0; bH[2 * nb][1] = r1;
                bH[2 * nb + 1][0] = r2; bH[2 * nb + 1][1] = r3;
                if (MODE == 0) {
                    ldm4(sBl + off, r0, r1, r2, r3);
                    bL[2 * nb][0] = r0; bL[2 * nb][1] = r1;
                    bL[2 * nb + 1][0] = r2; bL[2 * nb + 1][1] = r3;
                }
            }
#pragma unroll
            for (int mi = 0; mi < 4; mi++) {
                uint32_t aH[4];
                const uint32_t off =
                    (uint32_t)((wm + mi * 16 + a_row) * ROWB + (k0 + a_koff) * 2);
                ldm4(sAh + off, aH[0], aH[1], aH[2], aH[3]);
#pragma unroll
                for (int ni = 0; ni < 8; ni++) mma16816(acc[mi][ni], aH, bH[ni]);
                if (MODE == 0) {
#pragma unroll
                    for (int ni = 0; ni < 8; ni++) mma16816(acc[mi][ni], aH, bL[ni]);
                }
            }

            // between the two k0 steps: store next-A (fp32 path also loads B)
            if (k0 == 0 && pfv) {
                if (MODE == 0) {
                    half_store_A32(pf, nstg, t);
                    half_load(pf, B32, K, col0, kb, t);
                } else {
                    half_store_h(pfh, nstg, t);
                }
            }
        }

        if (pfv) {
            if (MODE == 0) half_store_B32(pf, nstg + MAT_BYTES, nstg + 2 * MAT_BYTES, t);
            else           half_store_h(pfh + 4, nstg + MAT_BYTES, t);
        }
        __syncthreads();
    }

    // Epilogue: fragments -> padded smem -> (scatter) gmem
    float* Csh = (float*)smem;                     // 128 x 130 fp32 (66.6 KB)
#pragma unroll
    for (int mi = 0; mi < 4; mi++)
#pragma unroll
        for (int ni = 0; ni < 8; ni++) {
            const int r = wm + mi * 16 + (l >> 2);
            const int c = wn + ni * 8 + (l & 3) * 2;
            float d0 = acc[mi][ni][0], d1 = acc[mi][ni][1];
            float d2 = acc[mi][ni][2], d3 = acc[mi][ni][3];
            if (MODE == 1) { d0 *= SCALE; d1 *= SCALE; d2 *= SCALE; d3 *= SCALE; }
            Csh[r * 130 + c]           = d0;
            Csh[r * 130 + c + 1]       = d1;
            Csh[(r + 8) * 130 + c]     = d2;
            Csh[(r + 8) * 130 + c + 1] = d3;
        }
    __syncthreads();

    for (int i = t; i < 128 * 128; i += 128) {
        const int r = i >> 7, c = i & 127;
        const float v = Csh[r * 130 + c];
        if (MODE == 0) {
            const int grow = row0 + r;
            const int col = col0 + c;
            const int which = col % 3;             // qkv reshape (d,3)
            const int oc = col / 3;
            if (which == 0)      g_Q16[(size_t)grow * DIM + oc] = __float2half_rn(v);
            else if (which == 1) g_K16[(size_t)grow * DIM + oc] = __float2half_rn(v);
            else {
                const int b = grow >> 11, tt = grow & 2047;
                g_V16t[((size_t)b * DIM + oc) * SEQ + tt] = __float2half_rn(v);
            }
        } else if (MODE == 1) {
            C[(size_t)(row0 + r) * SEQ + col0 + c] = v;
        } else {
            C[(size_t)(row0 + r) * DIM + col0 + c] = v;
        }
    }
}

// ---------------------------------------------------------------------------
// Row softmax: g_S row (2048 fp32) -> g_P fp16. 8 consecutive per thread.
// ---------------------------------------------------------------------------
__global__ __launch_bounds__(256) void softmax_k() {
    const size_t base = (size_t)blockIdx.x * SEQ;
    const float* p = g_S + base;
    const int t = threadIdx.x;
    const int lane = t & 31;
    const int warp = t >> 5;
    __shared__ float red[2][8];

    const float4 a = *(const float4*)(p + t * 8);
    const float4 b = *(const float4*)(p + t * 8 + 4);
    float v[8] = {a.x, a.y, a.z, a.w, b.x, b.y, b.z, b.w};

    float m = -1e30f;
#pragma unroll
    for (int i = 0; i < 8; i++) m = fmaxf(m, v[i]);
#pragma unroll
    for (int off = 16; off > 0; off >>= 1)
        m = fmaxf(m, __shfl_xor_sync(0xffffffffu, m, off));
    if (lane == 0) red[0][warp] = m;
    __syncthreads();
    m = red[0][0];
#pragma unroll
    for (int w = 1; w < 8; w++) m = fmaxf(m, red[0][w]);

    float s = 0.0f;
#pragma unroll
    for (int i = 0; i < 8; i++) { v[i] = __expf(v[i] - m); s += v[i]; }
#pragma unroll
    for (int off = 16; off > 0; off >>= 1)
        s += __shfl_xor_sync(0xffffffffu, s, off);
    if (lane == 0) red[1][warp] = s;
    __syncthreads();
    s = red[1][0];
#pragma unroll
    for (int w = 1; w < 8; w++) s += red[1][w];

    const float inv = 1.0f / s;
    __half h[8];
#pragma unroll
    for (int i = 0; i < 8; i++) h[i] = __float2half_rn(v[i] * inv);
    *(uint4*)(g_P + base + t * 8) = *(const uint4*)h;
}

// ---------------------------------------------------------------------------
extern "C" void kernel_launch(void* const* d_in, const int* in_sizes, int n_in,
                              void* d_out, int out_size) {
    const float* x = (const float*)d_in[0];    // [4, 2048, 1024]
    const float* W = (const float*)d_in[1];    // [3072, 1024]
    float* out = (float*)d_out;                // [4, 2048, 1024]

    cudaFuncSetAttribute(mma_gemm<0>, cudaFuncAttributeMaxDynamicSharedMemorySize, SMEM_BYTES);
    cudaFuncSetAttribute(mma_gemm<1>, cudaFuncAttributeMaxDynamicSharedMemorySize, SMEM_BYTES);
    cudaFuncSetAttribute(mma_gemm<2>, cudaFuncAttributeMaxDynamicSharedMemorySize, SMEM_BYTES);

    // 1) QKV projection (2-term W split; emits fp16 Q / K / V^T)
    mma_gemm<0><<<dim3(NQKV / 128, (BATCH * SEQ) / 128, 1), 128, SMEM_BYTES>>>(x, W, nullptr);
    // 2) scores = Q K^T * scale  (single-term fp16)
    mma_gemm<1><<<dim3(SEQ / 128, SEQ / 128, BATCH), 128, SMEM_BYTES>>>(nullptr, nullptr, nullptr);
    // 3) row softmax -> fp16 P
    softmax_k<<<dim3(BATCH * SEQ), 256>>>();
    // 4) out = P V  (single-term fp16)
    mma_gemm<2><<<dim3(DIM / 128, SEQ / 128, BATCH), 128, SMEM_BYTES>>>(nullptr, nullptr, out);
}